// round 2
// baseline (speedup 1.0000x reference)
#include <cuda_runtime.h>
#include <cstdint>
#include <cstddef>

// ---------------------------------------------------------------------------
// MambaBlock: b=2, L=1024, d_model=1024, d_inner=2048, d_state=16, d_conv=4
// Pipeline: GEMM1 -> conv+silu gate -> xproj GEMM -> selective scan -> GEMM2
// ---------------------------------------------------------------------------

namespace {
constexpr int kDI   = 2048;   // d_inner
constexpr int kDS   = 16;     // d_state
constexpr int kL    = 1024;   // sequence length
constexpr int kB    = 2;      // batch
constexpr int kDM   = 1024;   // d_model
constexpr int kRows = kB * kL;        // 2048 flattened rows
constexpr int kNP   = 2 * kDS + 1;    // 33 projection outputs
}

// Scratch (static device globals: allocation-free rule)
__device__ float g_xz[(size_t)kRows * 2 * kDI];   // 2048 x 4096
__device__ float g_xh[(size_t)kRows * kDI];       // gated conv output
__device__ float g_proj[(size_t)kRows * kNP];     // [dlt | B | C]
__device__ float g_y[(size_t)kRows * kDI];        // scan output + D*xh

// ---------------------------------------------------------------------------
// NT GEMM: C[m,n] = sum_k A[m,k] * B[n,k] (+ bias[n])
// 128x128 tile, BK=8, 256 threads, 8x8 per-thread microtile.
// M, N multiples of 128; K multiple of 8 (holds for all uses here).
// ---------------------------------------------------------------------------
template <bool BIAS>
__global__ void __launch_bounds__(256)
gemm_nt_kernel(const float* __restrict__ A, const float* __restrict__ B,
               const float* __restrict__ bias, float* __restrict__ C,
               int K, int N)
{
    __shared__ float As[8][128];
    __shared__ float Bs[8][128];

    const int tid = threadIdx.x;
    const int m0 = blockIdx.y * 128;
    const int n0 = blockIdx.x * 128;

    const int lr = tid >> 1;          // 0..127: tile row to load
    const int lc = (tid & 1) * 4;     // 0 or 4: k offset (float4)
    const int tx = tid & 15;          // 0..15
    const int ty = tid >> 4;          // 0..15

    float acc[8][8];
#pragma unroll
    for (int i = 0; i < 8; i++)
#pragma unroll
        for (int j = 0; j < 8; j++) acc[i][j] = 0.0f;

    const float* Ap = A + (size_t)(m0 + lr) * K + lc;
    const float* Bp = B + (size_t)(n0 + lr) * K + lc;

    for (int k0 = 0; k0 < K; k0 += 8) {
        float4 av = *(const float4*)(Ap + k0);
        float4 bv = *(const float4*)(Bp + k0);
        As[lc + 0][lr] = av.x; As[lc + 1][lr] = av.y;
        As[lc + 2][lr] = av.z; As[lc + 3][lr] = av.w;
        Bs[lc + 0][lr] = bv.x; Bs[lc + 1][lr] = bv.y;
        Bs[lc + 2][lr] = bv.z; Bs[lc + 3][lr] = bv.w;
        __syncthreads();

#pragma unroll
        for (int kk = 0; kk < 8; kk++) {
            float ra[8], rb[8];
#pragma unroll
            for (int i = 0; i < 8; i++) ra[i] = As[kk][ty * 8 + i];
#pragma unroll
            for (int j = 0; j < 8; j++) rb[j] = Bs[kk][tx * 8 + j];
#pragma unroll
            for (int i = 0; i < 8; i++)
#pragma unroll
                for (int j = 0; j < 8; j++) acc[i][j] += ra[i] * rb[j];
        }
        __syncthreads();
    }

#pragma unroll
    for (int i = 0; i < 8; i++) {
        const int row = m0 + ty * 8 + i;
#pragma unroll
        for (int j = 0; j < 8; j++) {
            const int col = n0 + tx * 8 + j;
            float v = acc[i][j];
            if (BIAS) v += bias[col];
            C[(size_t)row * N + col] = v;
        }
    }
}

// ---------------------------------------------------------------------------
// Depthwise causal conv (D_CONV=4) + bias + SiLU(z) gate.
// Reads g_xz ([xh | z] layout), writes g_xh.
// ---------------------------------------------------------------------------
__global__ void __launch_bounds__(256)
conv_gate_kernel(const float* __restrict__ conv_w,   // (2048,1,4)
                 const float* __restrict__ conv_b)   // (2048,)
{
    const int idx = blockIdx.x * 256 + threadIdx.x;  // over kB*kL*kDI
    const int i = idx & (kDI - 1);
    const int t = (idx >> 11) & (kL - 1);
    const int b = idx >> 21;

    const float* base = g_xz + (size_t)b * kL * (2 * kDI) + i;  // column i, xh half
    float accv = conv_b[i];
#pragma unroll
    for (int k = 0; k < 4; k++) {
        const int tt = t + k - 3;
        if (tt >= 0) accv += conv_w[i * 4 + k] * base[(size_t)tt * (2 * kDI)];
    }
    const float z = g_xz[((size_t)(b * kL + t)) * (2 * kDI) + kDI + i];
    const float sig = 1.0f / (1.0f + __expf(-z));
    g_xh[idx] = accv * (z * sig);
}

// ---------------------------------------------------------------------------
// proj = xh @ xproj_w^T  (per-row 33 dot products of length 2048)
// One block (256 threads) per row. xproj_w (270KB) stays L2-resident.
// ---------------------------------------------------------------------------
__global__ void __launch_bounds__(256)
proj_kernel(const float* __restrict__ w)  // (33, 2048)
{
    const int row = blockIdx.x;
    const float* xr = g_xh + (size_t)row * kDI;

    float acc[kNP];
#pragma unroll
    for (int n = 0; n < kNP; n++) acc[n] = 0.0f;

    for (int k = threadIdx.x; k < kDI; k += 256) {
        const float xv = xr[k];
#pragma unroll
        for (int n = 0; n < kNP; n++) acc[n] += xv * w[n * kDI + k];
    }

    // warp reduce
#pragma unroll
    for (int n = 0; n < kNP; n++) {
#pragma unroll
        for (int off = 16; off > 0; off >>= 1)
            acc[n] += __shfl_xor_sync(0xFFFFFFFFu, acc[n], off);
    }

    __shared__ float red[kNP][8];
    const int warp = threadIdx.x >> 5;
    const int lane = threadIdx.x & 31;
    if (lane == 0) {
#pragma unroll
        for (int n = 0; n < kNP; n++) red[n][warp] = acc[n];
    }
    __syncthreads();
    if (threadIdx.x < kNP) {
        float s = 0.0f;
#pragma unroll
        for (int w8 = 0; w8 < 8; w8++) s += red[threadIdx.x][w8];
        g_proj[(size_t)row * kNP + threadIdx.x] = s;
    }
}

// ---------------------------------------------------------------------------
// Selective scan. One thread per (batch, channel): h[16] in registers.
// delta = exp(softplus(x)) = 1 + exp(x)  (exact identity).
// Block = 256 channels of one batch; proj rows staged in smem per 64-t chunk.
// ---------------------------------------------------------------------------
__global__ void __launch_bounds__(256)
scan_kernel(const float* __restrict__ dt_w,   // (2048,1)
            const float* __restrict__ dt_b,   // (2048,)
            const float* __restrict__ A_log,  // (2048,16)
            const float* __restrict__ Dv)     // (2048,)
{
    constexpr int CHUNK = 64;
    const int b = blockIdx.x >> 3;
    const int i = ((blockIdx.x & 7) << 8) + threadIdx.x;

    float Arow[kDS], h[kDS];
#pragma unroll
    for (int s = 0; s < kDS; s++) {
        Arow[s] = -__expf(A_log[i * kDS + s]);
        h[s] = 0.0f;
    }
    const float dtw = dt_w[i];
    const float dtb = dt_b[i];
    const float Di  = Dv[i];

    __shared__ float sp[CHUNK * kNP];

    for (int t0 = 0; t0 < kL; t0 += CHUNK) {
        for (int idx = threadIdx.x; idx < CHUNK * kNP; idx += 256)
            sp[idx] = g_proj[((size_t)(b * kL + t0)) * kNP + idx];
        __syncthreads();

        for (int tt = 0; tt < CHUNK; tt++) {
            const int t = t0 + tt;
            const float* row = sp + tt * kNP;
            const float xt = g_xh[((size_t)(b * kL + t)) * kDI + i];
            const float delta = 1.0f + __expf(row[0] * dtw + dtb);
            float yv = 0.0f;
#pragma unroll
            for (int s = 0; s < kDS; s++) {
                const float Bt = row[1 + s];
                const float Ct = row[1 + kDS + s];
                h[s] = __expf(Arow[s] * delta) * h[s] + (delta * Bt) * xt;
                yv += h[s] * Ct;
            }
            g_y[((size_t)(b * kL + t)) * kDI + i] = yv + Di * xt;
        }
        __syncthreads();
    }
}

// ---------------------------------------------------------------------------
// Launch
// ---------------------------------------------------------------------------
extern "C" void kernel_launch(void* const* d_in, const int* in_sizes, int n_in,
                              void* d_out, int out_size)
{
    const float* x       = (const float*)d_in[0];   // (2,1024,1024)
    const float* in_w    = (const float*)d_in[1];   // (4096,1024)
    const float* in_b    = (const float*)d_in[2];   // (4096,)
    const float* conv_w  = (const float*)d_in[3];   // (2048,1,4)
    const float* conv_b  = (const float*)d_in[4];   // (2048,)
    const float* xproj_w = (const float*)d_in[5];   // (33,2048)
    const float* dt_w    = (const float*)d_in[6];   // (2048,1)
    const float* dt_b    = (const float*)d_in[7];   // (2048,)
    const float* A_log   = (const float*)d_in[8];   // (2048,16)
    const float* Dv      = (const float*)d_in[9];   // (2048,)
    const float* out_w   = (const float*)d_in[10];  // (1024,2048)
    float* out = (float*)d_out;                     // (2,1024,1024)

    float *xz_p, *y_p;
    cudaGetSymbolAddress((void**)&xz_p, g_xz);
    cudaGetSymbolAddress((void**)&y_p,  g_y);

    // GEMM1: xz = x @ in_w^T + in_b   (M=2048, N=4096, K=1024)
    {
        dim3 grid((2 * kDI) / 128, kRows / 128);
        gemm_nt_kernel<true><<<grid, 256>>>(x, in_w, in_b, xz_p, kDM, 2 * kDI);
    }
    // conv + SiLU gate
    conv_gate_kernel<<<(kRows * kDI) / 256, 256>>>(conv_w, conv_b);
    // xproj: proj = xh @ xproj_w^T  (33 outputs per row)
    proj_kernel<<<kRows, 256>>>(xproj_w);
    // selective scan
    scan_kernel<<<(kB * kDI) / 256, 256>>>(dt_w, dt_b, A_log, Dv);
    // GEMM2: out = y @ out_w^T  (M=2048, N=1024, K=2048)
    {
        dim3 grid(kDM / 128, kRows / 128);
        gemm_nt_kernel<false><<<grid, 256>>>(y_p, out_w, nullptr, out, kDI, kDM);
    }
}

// round 3
// speedup vs baseline: 1.2509x; 1.2509x over previous
#include <cuda_runtime.h>
#include <cstdint>
#include <cstddef>

// ---------------------------------------------------------------------------
// MambaBlock: b=2, L=1024, d_model=1024, d_inner=2048, d_state=16, d_conv=4
// GEMM1 -> conv+silu gate -> xproj -> chunked selective scan (3 kernels) -> GEMM2
// ---------------------------------------------------------------------------

namespace {
constexpr int kDI   = 2048;   // d_inner
constexpr int kDS   = 16;     // d_state
constexpr int kL    = 1024;   // sequence length
constexpr int kB    = 2;      // batch
constexpr int kDM   = 1024;   // d_model
constexpr int kRows = kB * kL;        // 2048 flattened rows
constexpr int kNP   = 2 * kDS + 1;    // 33 projection outputs
constexpr int kNCH  = 32;             // scan chunks
constexpr int kTCH  = kL / kNCH;      // 32 steps per chunk
}

// Scratch (static device globals: allocation-free rule)
__device__ float g_xz[(size_t)kRows * 2 * kDI];   // 2048 x 4096
__device__ float g_xh[(size_t)kRows * kDI];       // gated conv output
__device__ float g_proj[(size_t)kRows * kNP];     // [dlt | B | C]
__device__ float g_y[(size_t)kRows * kDI];        // scan output + D*xh
__device__ float g_aprod [(size_t)kB * kNCH * kDI * kDS];
__device__ float g_hloc  [(size_t)kB * kNCH * kDI * kDS];
__device__ float g_hstart[(size_t)kB * kNCH * kDI * kDS];

// ---------------------------------------------------------------------------
// NT GEMM: C[m,n] = sum_k A[m,k] * B[n,k] (+ bias[n])
// 128x128 tile, BK=8, 256 threads, 8x8 per-thread microtile.
// ---------------------------------------------------------------------------
template <bool BIAS>
__global__ void __launch_bounds__(256)
gemm_nt_kernel(const float* __restrict__ A, const float* __restrict__ B,
               const float* __restrict__ bias, float* __restrict__ C,
               int K, int N)
{
    __shared__ float As[8][128];
    __shared__ float Bs[8][128];

    const int tid = threadIdx.x;
    const int m0 = blockIdx.y * 128;
    const int n0 = blockIdx.x * 128;

    const int lr = tid >> 1;          // 0..127: tile row to load
    const int lc = (tid & 1) * 4;     // 0 or 4: k offset (float4)
    const int tx = tid & 15;          // 0..15
    const int ty = tid >> 4;          // 0..15

    float acc[8][8];
#pragma unroll
    for (int i = 0; i < 8; i++)
#pragma unroll
        for (int j = 0; j < 8; j++) acc[i][j] = 0.0f;

    const float* Ap = A + (size_t)(m0 + lr) * K + lc;
    const float* Bp = B + (size_t)(n0 + lr) * K + lc;

    for (int k0 = 0; k0 < K; k0 += 8) {
        float4 av = *(const float4*)(Ap + k0);
        float4 bv = *(const float4*)(Bp + k0);
        As[lc + 0][lr] = av.x; As[lc + 1][lr] = av.y;
        As[lc + 2][lr] = av.z; As[lc + 3][lr] = av.w;
        Bs[lc + 0][lr] = bv.x; Bs[lc + 1][lr] = bv.y;
        Bs[lc + 2][lr] = bv.z; Bs[lc + 3][lr] = bv.w;
        __syncthreads();

#pragma unroll
        for (int kk = 0; kk < 8; kk++) {
            float ra[8], rb[8];
#pragma unroll
            for (int i = 0; i < 8; i++) ra[i] = As[kk][ty * 8 + i];
#pragma unroll
            for (int j = 0; j < 8; j++) rb[j] = Bs[kk][tx * 8 + j];
#pragma unroll
            for (int i = 0; i < 8; i++)
#pragma unroll
                for (int j = 0; j < 8; j++) acc[i][j] += ra[i] * rb[j];
        }
        __syncthreads();
    }

#pragma unroll
    for (int i = 0; i < 8; i++) {
        const int row = m0 + ty * 8 + i;
#pragma unroll
        for (int j = 0; j < 8; j++) {
            const int col = n0 + tx * 8 + j;
            float v = acc[i][j];
            if (BIAS) v += bias[col];
            C[(size_t)row * N + col] = v;
        }
    }
}

// ---------------------------------------------------------------------------
// Depthwise causal conv (D_CONV=4) + bias + SiLU(z) gate.
// ---------------------------------------------------------------------------
__global__ void __launch_bounds__(256)
conv_gate_kernel(const float* __restrict__ conv_w,   // (2048,1,4)
                 const float* __restrict__ conv_b)   // (2048,)
{
    const int idx = blockIdx.x * 256 + threadIdx.x;  // over kB*kL*kDI
    const int i = idx & (kDI - 1);
    const int t = (idx >> 11) & (kL - 1);
    const int b = idx >> 21;

    const float* base = g_xz + (size_t)b * kL * (2 * kDI) + i;  // column i, xh half
    float accv = conv_b[i];
#pragma unroll
    for (int k = 0; k < 4; k++) {
        const int tt = t + k - 3;
        if (tt >= 0) accv += conv_w[i * 4 + k] * base[(size_t)tt * (2 * kDI)];
    }
    const float z = g_xz[((size_t)(b * kL + t)) * (2 * kDI) + kDI + i];
    const float sig = 1.0f / (1.0f + __expf(-z));
    g_xh[idx] = accv * (z * sig);
}

// ---------------------------------------------------------------------------
// proj = xh @ xproj_w^T  (per-row 33 dot products of length 2048)
// ---------------------------------------------------------------------------
__global__ void __launch_bounds__(256)
proj_kernel(const float* __restrict__ w)  // (33, 2048)
{
    const int row = blockIdx.x;
    const float* xr = g_xh + (size_t)row * kDI;

    float acc[kNP];
#pragma unroll
    for (int n = 0; n < kNP; n++) acc[n] = 0.0f;

    for (int k = threadIdx.x; k < kDI; k += 256) {
        const float xv = xr[k];
#pragma unroll
        for (int n = 0; n < kNP; n++) acc[n] += xv * w[n * kDI + k];
    }

#pragma unroll
    for (int n = 0; n < kNP; n++) {
#pragma unroll
        for (int off = 16; off > 0; off >>= 1)
            acc[n] += __shfl_xor_sync(0xFFFFFFFFu, acc[n], off);
    }

    __shared__ float red[kNP][8];
    const int warp = threadIdx.x >> 5;
    const int lane = threadIdx.x & 31;
    if (lane == 0) {
#pragma unroll
        for (int n = 0; n < kNP; n++) red[n][warp] = acc[n];
    }
    __syncthreads();
    if (threadIdx.x < kNP) {
        float s = 0.0f;
#pragma unroll
        for (int w8 = 0; w8 < 8; w8++) s += red[threadIdx.x][w8];
        g_proj[(size_t)row * kNP + threadIdx.x] = s;
    }
}

// ---------------------------------------------------------------------------
// Chunked selective scan.
// h_t = a_t * h_{t-1} + b_t  (diagonal per (b,i,s)) is chunked into kNCH
// chunks of kTCH steps:
//   pass1: per chunk, compute (prod a, h_local with h0=0)
//   combine: tiny sequential scan over chunks -> h_start per chunk
//   pass3: replay each chunk from its h_start, emit y
// delta = exp(softplus(x)) = 1 + exp(x)  (exact identity).
// ---------------------------------------------------------------------------
__global__ void __launch_bounds__(256)
scan_pass1_kernel(const float* __restrict__ dt_w,   // (2048,1)
                  const float* __restrict__ dt_b,   // (2048,)
                  const float* __restrict__ A_log)  // (2048,16)
{
    // grid = kB * kNCH * (kDI/256)
    const int gi = blockIdx.x;
    const int b = gi / (kNCH * (kDI / 256));
    const int c = (gi / (kDI / 256)) % kNCH;
    const int i = (gi % (kDI / 256)) * 256 + threadIdx.x;

    float Arow[kDS], h[kDS], P[kDS];
#pragma unroll
    for (int s = 0; s < kDS; s++) {
        Arow[s] = -__expf(A_log[i * kDS + s]);
        h[s] = 0.0f;
        P[s] = 1.0f;
    }
    const float dtw = dt_w[i];
    const float dtb = dt_b[i];

    __shared__ float sp[kTCH * kNP];
    {
        const size_t base = (size_t)(b * kL + c * kTCH) * kNP;
        for (int idx = threadIdx.x; idx < kTCH * kNP; idx += 256)
            sp[idx] = g_proj[base + idx];
    }
    __syncthreads();

    for (int tt = 0; tt < kTCH; tt++) {
        const int t = c * kTCH + tt;
        const float* row = sp + tt * kNP;
        const float xt = g_xh[((size_t)(b * kL + t)) * kDI + i];
        const float delta = 1.0f + __expf(row[0] * dtw + dtb);
        const float dx = delta * xt;
#pragma unroll
        for (int s = 0; s < kDS; s++) {
            const float a = __expf(Arow[s] * delta);
            h[s] = a * h[s] + row[1 + s] * dx;
            P[s] *= a;
        }
    }

    const size_t o = (((size_t)(b * kNCH + c)) * kDI + i) * kDS;
#pragma unroll
    for (int v = 0; v < kDS / 4; v++) {
        *(float4*)(g_aprod + o + v * 4) = make_float4(P[v*4], P[v*4+1], P[v*4+2], P[v*4+3]);
        *(float4*)(g_hloc  + o + v * 4) = make_float4(h[v*4], h[v*4+1], h[v*4+2], h[v*4+3]);
    }
}

__global__ void __launch_bounds__(256)
scan_combine_kernel()
{
    const int idx = blockIdx.x * 256 + threadIdx.x;  // over kB*kDI*kDS = 65536
    const int b = idx >> 15;
    const int rem = idx & ((kDI * kDS) - 1);         // i*kDS + s
    float h = 0.0f;
#pragma unroll 4
    for (int c = 0; c < kNCH; c++) {
        const size_t o = ((size_t)(b * kNCH + c)) * (kDI * kDS) + rem;
        g_hstart[o] = h;
        h = g_aprod[o] * h + g_hloc[o];
    }
}

__global__ void __launch_bounds__(256)
scan_pass3_kernel(const float* __restrict__ dt_w,   // (2048,1)
                  const float* __restrict__ dt_b,   // (2048,)
                  const float* __restrict__ A_log,  // (2048,16)
                  const float* __restrict__ Dv)     // (2048,)
{
    const int gi = blockIdx.x;
    const int b = gi / (kNCH * (kDI / 256));
    const int c = (gi / (kDI / 256)) % kNCH;
    const int i = (gi % (kDI / 256)) * 256 + threadIdx.x;

    float Arow[kDS], h[kDS];
    {
        const size_t o = (((size_t)(b * kNCH + c)) * kDI + i) * kDS;
#pragma unroll
        for (int v = 0; v < kDS / 4; v++) {
            float4 hv = *(const float4*)(g_hstart + o + v * 4);
            h[v*4] = hv.x; h[v*4+1] = hv.y; h[v*4+2] = hv.z; h[v*4+3] = hv.w;
        }
    }
#pragma unroll
    for (int s = 0; s < kDS; s++)
        Arow[s] = -__expf(A_log[i * kDS + s]);

    const float dtw = dt_w[i];
    const float dtb = dt_b[i];
    const float Di  = Dv[i];

    __shared__ float sp[kTCH * kNP];
    {
        const size_t base = (size_t)(b * kL + c * kTCH) * kNP;
        for (int idx = threadIdx.x; idx < kTCH * kNP; idx += 256)
            sp[idx] = g_proj[base + idx];
    }
    __syncthreads();

    for (int tt = 0; tt < kTCH; tt++) {
        const int t = c * kTCH + tt;
        const float* row = sp + tt * kNP;
        const float xt = g_xh[((size_t)(b * kL + t)) * kDI + i];
        const float delta = 1.0f + __expf(row[0] * dtw + dtb);
        const float dx = delta * xt;
        float yv = 0.0f;
#pragma unroll
        for (int s = 0; s < kDS; s++) {
            const float a = __expf(Arow[s] * delta);
            h[s] = a * h[s] + row[1 + s] * dx;
            yv += h[s] * row[1 + kDS + s];
        }
        g_y[((size_t)(b * kL + t)) * kDI + i] = yv + Di * xt;
    }
}

// ---------------------------------------------------------------------------
// Launch
// ---------------------------------------------------------------------------
extern "C" void kernel_launch(void* const* d_in, const int* in_sizes, int n_in,
                              void* d_out, int out_size)
{
    const float* x       = (const float*)d_in[0];   // (2,1024,1024)
    const float* in_w    = (const float*)d_in[1];   // (4096,1024)
    const float* in_b    = (const float*)d_in[2];   // (4096,)
    const float* conv_w  = (const float*)d_in[3];   // (2048,1,4)
    const float* conv_b  = (const float*)d_in[4];   // (2048,)
    const float* xproj_w = (const float*)d_in[5];   // (33,2048)
    const float* dt_w    = (const float*)d_in[6];   // (2048,1)
    const float* dt_b    = (const float*)d_in[7];   // (2048,)
    const float* A_log   = (const float*)d_in[8];   // (2048,16)
    const float* Dv      = (const float*)d_in[9];   // (2048,)
    const float* out_w   = (const float*)d_in[10];  // (1024,2048)
    float* out = (float*)d_out;                     // (2,1024,1024)

    float *xz_p, *y_p;
    cudaGetSymbolAddress((void**)&xz_p, g_xz);
    cudaGetSymbolAddress((void**)&y_p,  g_y);

    // GEMM1: xz = x @ in_w^T + in_b   (M=2048, N=4096, K=1024)
    {
        dim3 grid((2 * kDI) / 128, kRows / 128);
        gemm_nt_kernel<true><<<grid, 256>>>(x, in_w, in_b, xz_p, kDM, 2 * kDI);
    }
    // conv + SiLU gate
    conv_gate_kernel<<<(kRows * kDI) / 256, 256>>>(conv_w, conv_b);
    // xproj: proj = xh @ xproj_w^T  (33 outputs per row)
    proj_kernel<<<kRows, 256>>>(xproj_w);
    // chunked selective scan
    {
        const int grid_scan = kB * kNCH * (kDI / 256);   // 512
        scan_pass1_kernel<<<grid_scan, 256>>>(dt_w, dt_b, A_log);
        scan_combine_kernel<<<(kB * kDI * kDS) / 256, 256>>>();
        scan_pass3_kernel<<<grid_scan, 256>>>(dt_w, dt_b, A_log, Dv);
    }
    // GEMM2: out = y @ out_w^T  (M=2048, N=1024, K=2048)
    {
        dim3 grid(kDM / 128, kRows / 128);
        gemm_nt_kernel<false><<<grid, 256>>>(y_p, out_w, nullptr, out, kDI, kDM);
    }
}

// round 5
// speedup vs baseline: 2.6974x; 2.1564x over previous
#include <cuda_runtime.h>
#include <cuda_bf16.h>
#include <cstdint>
#include <cstddef>

// ---------------------------------------------------------------------------
// MambaBlock: b=2, L=1024, d_model=1024, d_inner=2048, d_state=16, d_conv=4
// bf16x3 mma.sync GEMMs + conv/gate + xproj + chunked selective scan
// ---------------------------------------------------------------------------

namespace {
constexpr int kDI   = 2048;
constexpr int kDS   = 16;
constexpr int kL    = 1024;
constexpr int kB    = 2;
constexpr int kDM   = 1024;
constexpr int kRows = kB * kL;        // 2048
constexpr int kNP   = 2 * kDS + 1;    // 33
constexpr int kNCH  = 32;             // scan chunks
constexpr int kTCH  = kL / kNCH;      // 32

// GEMM smem: 4 matrices (Ahi,Alo,Bhi,Blo), 128 rows x 40 bf16 (80B, padded)
constexpr int SROWB  = 80;                    // bytes per smem row
constexpr int MATB   = 128 * SROWB;           // 10240
constexpr int STAGEB = 4 * MATB;              // 40960
constexpr int STAGES = 3;
constexpr int TC_SMEM = STAGES * STAGEB;      // 122880
}

// Scratch (allocation-free rule: device globals)
__device__ float g_xz[(size_t)kRows * 2 * kDI];
__device__ float g_xh[(size_t)kRows * kDI];
__device__ float g_proj[(size_t)kRows * kNP];
__device__ float g_aprod [(size_t)kB * kNCH * kDI * kDS];
__device__ float g_hloc  [(size_t)kB * kNCH * kDI * kDS];
__device__ float g_hstart[(size_t)kB * kNCH * kDI * kDS];
// bf16 hi/lo operand buffers (stored as ushort to keep trivial init)
__device__ unsigned short g_xhi [(size_t)kRows * kDM];
__device__ unsigned short g_xlo [(size_t)kRows * kDM];
__device__ unsigned short g_wihi[(size_t)2 * kDI * kDM];
__device__ unsigned short g_wilo[(size_t)2 * kDI * kDM];
__device__ unsigned short g_wohi[(size_t)kDM * kDI];
__device__ unsigned short g_wolo[(size_t)kDM * kDI];
__device__ unsigned short g_yhi [(size_t)kRows * kDI];
__device__ unsigned short g_ylo [(size_t)kRows * kDI];

// ---------------------------------------------------------------------------
// PTX helpers (sm_103 base feature set only: cp.async, ldmatrix, mma.sync)
// ---------------------------------------------------------------------------
__device__ __forceinline__ uint32_t smem_u32(const void* p) {
    uint32_t a;
    asm("{ .reg .u64 t; cvta.to.shared.u64 t, %1; cvt.u32.u64 %0, t; }" : "=r"(a) : "l"(p));
    return a;
}
__device__ __forceinline__ void cp16(uint32_t saddr, const void* gaddr) {
    asm volatile("cp.async.cg.shared.global [%0], [%1], 16;" :: "r"(saddr), "l"(gaddr));
}
__device__ __forceinline__ void ldsm_x4(uint32_t a, uint32_t r[4]) {
    asm volatile("ldmatrix.sync.aligned.m8n8.x4.shared.b16 {%0,%1,%2,%3}, [%4];"
                 : "=r"(r[0]), "=r"(r[1]), "=r"(r[2]), "=r"(r[3]) : "r"(a));
}
__device__ __forceinline__ void ldsm_x2(uint32_t a, uint32_t r[2]) {
    asm volatile("ldmatrix.sync.aligned.m8n8.x2.shared.b16 {%0,%1}, [%2];"
                 : "=r"(r[0]), "=r"(r[1]) : "r"(a));
}
__device__ __forceinline__ void mma_bf16(float c[4], const uint32_t a[4], const uint32_t b[2]) {
    asm volatile(
        "mma.sync.aligned.m16n8k16.row.col.f32.bf16.bf16.f32 "
        "{%0,%1,%2,%3}, {%4,%5,%6,%7}, {%8,%9}, {%0,%1,%2,%3};"
        : "+f"(c[0]), "+f"(c[1]), "+f"(c[2]), "+f"(c[3])
        : "r"(a[0]), "r"(a[1]), "r"(a[2]), "r"(a[3]), "r"(b[0]), "r"(b[1]));
}

// ---------------------------------------------------------------------------
// float -> (bf16 hi, bf16 lo) split
// ---------------------------------------------------------------------------
__global__ void __launch_bounds__(256)
cvt_hilo_kernel(const float* __restrict__ in, unsigned short* __restrict__ hi,
                unsigned short* __restrict__ lo, int n)
{
    const int i = blockIdx.x * 256 + threadIdx.x;
    if (i >= n) return;
    const float x = in[i];
    const __nv_bfloat16 h = __float2bfloat16(x);
    hi[i] = __bfloat16_as_ushort(h);
    lo[i] = __bfloat16_as_ushort(__float2bfloat16(x - __bfloat162float(h)));
}

// ---------------------------------------------------------------------------
// bf16x3 NT GEMM: C[m,n] = sum_k A[m,k]*B[n,k] (+bias[n])
// A,B given as hi/lo bf16 [rows][K]. 128x128 CTA tile, 8 warps x (64x32),
// BK=32, 3-stage cp.async pipeline, ldmatrix fragments, m16n8k16 mma.
// ---------------------------------------------------------------------------
template <bool BIAS>
__global__ void __launch_bounds__(256)
gemm_bf16x3_kernel(const unsigned short* __restrict__ Ahi,
                   const unsigned short* __restrict__ Alo,
                   const unsigned short* __restrict__ Bhi,
                   const unsigned short* __restrict__ Blo,
                   const float* __restrict__ bias, float* __restrict__ C,
                   int K, int N)
{
    extern __shared__ char sm[];
    const uint32_t sbase = smem_u32(sm);
    const int tid  = threadIdx.x;
    const int wid  = tid >> 5;
    const int lane = tid & 31;
    const int m0 = blockIdx.y * 128;
    const int n0 = blockIdx.x * 128;
    const int wm = wid & 1;          // 2 row bands of 64
    const int wn = wid >> 1;         // 4 col bands of 32

    const unsigned short* mats[4] = {
        Ahi + (size_t)m0 * K, Alo + (size_t)m0 * K,
        Bhi + (size_t)n0 * K, Blo + (size_t)n0 * K };

    const int NK = K >> 5;

    // cp.async loader: thread t covers matrix (t>>6), 8 16B chunks
    const int lm = tid >> 6;
    const int lt = tid & 63;
    const unsigned short* gmat = mats[lm];

    auto issue_stage = [&](int kc) {
        const uint32_t sb = sbase + (uint32_t)(kc % STAGES) * STAGEB + lm * MATB;
        const char* gb = (const char*)(gmat) + (size_t)kc * 64;
#pragma unroll
        for (int j = 0; j < 8; j++) {
            const int id  = lt + j * 64;
            const int row = id >> 2;
            const int c16 = id & 3;
            cp16(sb + row * SROWB + c16 * 16, gb + (size_t)row * K * 2 + c16 * 16);
        }
    };

    // prologue: stage 0,1
    issue_stage(0);
    asm volatile("cp.async.commit_group;");
    issue_stage(1);
    asm volatile("cp.async.commit_group;");

    float acc[4][4][4];
#pragma unroll
    for (int mt = 0; mt < 4; mt++)
#pragma unroll
        for (int nt = 0; nt < 4; nt++)
#pragma unroll
            for (int r = 0; r < 4; r++) acc[mt][nt][r] = 0.0f;

    // ldmatrix lane-derived offsets
    const int ag = lane >> 3;                       // 0..3
    const int arow = (ag & 1) * 8 + (lane & 7);     // row within 16
    const int akb = (ag >> 1) * 16;                 // k-byte within 16B-halves
    const int brow = lane & 7;
    const int bkb = ((lane >> 3) & 1) * 16;

    for (int kc = 0; kc < NK; kc++) {
        asm volatile("cp.async.wait_group 1;");
        __syncthreads();

        const uint32_t stg = sbase + (uint32_t)(kc % STAGES) * STAGEB;
        const uint32_t aAhi = stg + 0 * MATB + (wm * 64) * SROWB + arow * SROWB + akb;
        const uint32_t aAlo = stg + 1 * MATB + (wm * 64) * SROWB + arow * SROWB + akb;
        const uint32_t aBhi = stg + 2 * MATB + (wn * 32) * SROWB + brow * SROWB + bkb;
        const uint32_t aBlo = stg + 3 * MATB + (wn * 32) * SROWB + brow * SROWB + bkb;

#pragma unroll
        for (int kh = 0; kh < 2; kh++) {
            const uint32_t ko = kh * 32;
            uint32_t fAh[4][4], fAl[4][4], fBh[4][2], fBl[4][2];
#pragma unroll
            for (int mt = 0; mt < 4; mt++) {
                ldsm_x4(aAhi + mt * 16 * SROWB + ko, fAh[mt]);
                ldsm_x4(aAlo + mt * 16 * SROWB + ko, fAl[mt]);
            }
#pragma unroll
            for (int nt = 0; nt < 4; nt++) {
                ldsm_x2(aBhi + nt * 8 * SROWB + ko, fBh[nt]);
                ldsm_x2(aBlo + nt * 8 * SROWB + ko, fBl[nt]);
            }
#pragma unroll
            for (int mt = 0; mt < 4; mt++)
#pragma unroll
                for (int nt = 0; nt < 4; nt++) {
                    mma_bf16(acc[mt][nt], fAh[mt], fBh[nt]);
                    mma_bf16(acc[mt][nt], fAh[mt], fBl[nt]);
                    mma_bf16(acc[mt][nt], fAl[mt], fBh[nt]);
                }
        }
        __syncthreads();
        if (kc + STAGES - 1 < NK) issue_stage(kc + STAGES - 1);
        asm volatile("cp.async.commit_group;");
    }

    // Epilogue: direct stores (c0,c1) / (c2,c3) as float2
    const int gid = lane >> 2;
    const int tig = lane & 3;
#pragma unroll
    for (int mt = 0; mt < 4; mt++) {
        const int r0 = m0 + wm * 64 + mt * 16 + gid;
#pragma unroll
        for (int nt = 0; nt < 4; nt++) {
            const int c = n0 + wn * 32 + nt * 8 + 2 * tig;
            float b0 = 0.0f, b1 = 0.0f;
            if (BIAS) { b0 = bias[c]; b1 = bias[c + 1]; }
            float2 v0 = make_float2(acc[mt][nt][0] + b0, acc[mt][nt][1] + b1);
            float2 v1 = make_float2(acc[mt][nt][2] + b0, acc[mt][nt][3] + b1);
            *(float2*)(&C[(size_t)r0 * N + c])       = v0;
            *(float2*)(&C[(size_t)(r0 + 8) * N + c]) = v1;
        }
    }
}

// ---------------------------------------------------------------------------
// Depthwise causal conv (D_CONV=4) + bias + SiLU(z) gate.
// ---------------------------------------------------------------------------
__global__ void __launch_bounds__(256)
conv_gate_kernel(const float* __restrict__ conv_w,
                 const float* __restrict__ conv_b)
{
    const int idx = blockIdx.x * 256 + threadIdx.x;
    const int i = idx & (kDI - 1);
    const int t = (idx >> 11) & (kL - 1);
    const int b = idx >> 21;

    const float* base = g_xz + (size_t)b * kL * (2 * kDI) + i;
    float accv = conv_b[i];
#pragma unroll
    for (int k = 0; k < 4; k++) {
        const int tt = t + k - 3;
        if (tt >= 0) accv += conv_w[i * 4 + k] * base[(size_t)tt * (2 * kDI)];
    }
    const float z = g_xz[((size_t)(b * kL + t)) * (2 * kDI) + kDI + i];
    const float sig = 1.0f / (1.0f + __expf(-z));
    g_xh[idx] = accv * (z * sig);
}

// ---------------------------------------------------------------------------
// proj = xh @ xproj_w^T
// ---------------------------------------------------------------------------
__global__ void __launch_bounds__(256)
proj_kernel(const float* __restrict__ w)
{
    const int row = blockIdx.x;
    const float* xr = g_xh + (size_t)row * kDI;

    float acc[kNP];
#pragma unroll
    for (int n = 0; n < kNP; n++) acc[n] = 0.0f;

    for (int k = threadIdx.x; k < kDI; k += 256) {
        const float xv = xr[k];
#pragma unroll
        for (int n = 0; n < kNP; n++) acc[n] += xv * w[n * kDI + k];
    }

#pragma unroll
    for (int n = 0; n < kNP; n++) {
#pragma unroll
        for (int off = 16; off > 0; off >>= 1)
            acc[n] += __shfl_xor_sync(0xFFFFFFFFu, acc[n], off);
    }

    __shared__ float red[kNP][8];
    const int warp = threadIdx.x >> 5;
    const int lane = threadIdx.x & 31;
    if (lane == 0) {
#pragma unroll
        for (int n = 0; n < kNP; n++) red[n][warp] = acc[n];
    }
    __syncthreads();
    if (threadIdx.x < kNP) {
        float s = 0.0f;
#pragma unroll
        for (int w8 = 0; w8 < 8; w8++) s += red[threadIdx.x][w8];
        g_proj[(size_t)row * kNP + threadIdx.x] = s;
    }
}

// ---------------------------------------------------------------------------
// Chunked selective scan. delta = exp(softplus(.)) = 1 + exp(.) identity.
// ---------------------------------------------------------------------------
__global__ void __launch_bounds__(256)
scan_pass1_kernel(const float* __restrict__ dt_w,
                  const float* __restrict__ dt_b,
                  const float* __restrict__ A_log)
{
    const int gi = blockIdx.x;
    const int b = gi / (kNCH * (kDI / 256));
    const int c = (gi / (kDI / 256)) % kNCH;
    const int i = (gi % (kDI / 256)) * 256 + threadIdx.x;

    float Arow[kDS], h[kDS], P[kDS];
#pragma unroll
    for (int s = 0; s < kDS; s++) {
        Arow[s] = -__expf(A_log[i * kDS + s]);
        h[s] = 0.0f;
        P[s] = 1.0f;
    }
    const float dtw = dt_w[i];
    const float dtb = dt_b[i];

    __shared__ float sp[kTCH * kNP];
    {
        const size_t base = (size_t)(b * kL + c * kTCH) * kNP;
        for (int idx = threadIdx.x; idx < kTCH * kNP; idx += 256)
            sp[idx] = g_proj[base + idx];
    }
    __syncthreads();

    for (int tt = 0; tt < kTCH; tt++) {
        const int t = c * kTCH + tt;
        const float* row = sp + tt * kNP;
        const float xt = g_xh[((size_t)(b * kL + t)) * kDI + i];
        const float delta = 1.0f + __expf(row[0] * dtw + dtb);
        const float dx = delta * xt;
#pragma unroll
        for (int s = 0; s < kDS; s++) {
            const float a = __expf(Arow[s] * delta);
            h[s] = a * h[s] + row[1 + s] * dx;
            P[s] *= a;
        }
    }

    const size_t o = (((size_t)(b * kNCH + c)) * kDI + i) * kDS;
#pragma unroll
    for (int v = 0; v < kDS / 4; v++) {
        *(float4*)(g_aprod + o + v * 4) = make_float4(P[v*4], P[v*4+1], P[v*4+2], P[v*4+3]);
        *(float4*)(g_hloc  + o + v * 4) = make_float4(h[v*4], h[v*4+1], h[v*4+2], h[v*4+3]);
    }
}

__global__ void __launch_bounds__(256)
scan_combine_kernel()
{
    const int idx = blockIdx.x * 256 + threadIdx.x;
    const int b = idx >> 15;
    const int rem = idx & ((kDI * kDS) - 1);
    float h = 0.0f;
#pragma unroll 4
    for (int c = 0; c < kNCH; c++) {
        const size_t o = ((size_t)(b * kNCH + c)) * (kDI * kDS) + rem;
        g_hstart[o] = h;
        h = g_aprod[o] * h + g_hloc[o];
    }
}

__global__ void __launch_bounds__(256)
scan_pass3_kernel(const float* __restrict__ dt_w,
                  const float* __restrict__ dt_b,
                  const float* __restrict__ A_log,
                  const float* __restrict__ Dv)
{
    const int gi = blockIdx.x;
    const int b = gi / (kNCH * (kDI / 256));
    const int c = (gi / (kDI / 256)) % kNCH;
    const int i = (gi % (kDI / 256)) * 256 + threadIdx.x;

    float Arow[kDS], h[kDS];
    {
        const size_t o = (((size_t)(b * kNCH + c)) * kDI + i) * kDS;
#pragma unroll
        for (int v = 0; v < kDS / 4; v++) {
            float4 hv = *(const float4*)(g_hstart + o + v * 4);
            h[v*4] = hv.x; h[v*4+1] = hv.y; h[v*4+2] = hv.z; h[v*4+3] = hv.w;
        }
    }
#pragma unroll
    for (int s = 0; s < kDS; s++)
        Arow[s] = -__expf(A_log[i * kDS + s]);

    const float dtw = dt_w[i];
    const float dtb = dt_b[i];
    const float Di  = Dv[i];

    __shared__ float sp[kTCH * kNP];
    {
        const size_t base = (size_t)(b * kL + c * kTCH) * kNP;
        for (int idx = threadIdx.x; idx < kTCH * kNP; idx += 256)
            sp[idx] = g_proj[base + idx];
    }
    __syncthreads();

    for (int tt = 0; tt < kTCH; tt++) {
        const int t = c * kTCH + tt;
        const float* row = sp + tt * kNP;
        const size_t oy = ((size_t)(b * kL + t)) * kDI + i;
        const float xt = g_xh[oy];
        const float delta = 1.0f + __expf(row[0] * dtw + dtb);
        const float dx = delta * xt;
        float yv = 0.0f;
#pragma unroll
        for (int s = 0; s < kDS; s++) {
            const float a = __expf(Arow[s] * delta);
            h[s] = a * h[s] + row[1 + s] * dx;
            yv += h[s] * row[1 + kDS + s];
        }
        const float yf = yv + Di * xt;
        const __nv_bfloat16 hy = __float2bfloat16(yf);
        g_yhi[oy] = __bfloat16_as_ushort(hy);
        g_ylo[oy] = __bfloat16_as_ushort(__float2bfloat16(yf - __bfloat162float(hy)));
    }
}

// ---------------------------------------------------------------------------
// Launch
// ---------------------------------------------------------------------------
extern "C" void kernel_launch(void* const* d_in, const int* in_sizes, int n_in,
                              void* d_out, int out_size)
{
    const float* x       = (const float*)d_in[0];
    const float* in_w    = (const float*)d_in[1];
    const float* in_b    = (const float*)d_in[2];
    const float* conv_w  = (const float*)d_in[3];
    const float* conv_b  = (const float*)d_in[4];
    const float* xproj_w = (const float*)d_in[5];
    const float* dt_w    = (const float*)d_in[6];
    const float* dt_b    = (const float*)d_in[7];
    const float* A_log   = (const float*)d_in[8];
    const float* Dv      = (const float*)d_in[9];
    const float* out_w   = (const float*)d_in[10];
    float* out = (float*)d_out;

    float* xz_p;
    unsigned short *xhi, *xlo, *wihi, *wilo, *wohi, *wolo, *yhi, *ylo;
    cudaGetSymbolAddress((void**)&xz_p, g_xz);
    cudaGetSymbolAddress((void**)&xhi,  g_xhi);
    cudaGetSymbolAddress((void**)&xlo,  g_xlo);
    cudaGetSymbolAddress((void**)&wihi, g_wihi);
    cudaGetSymbolAddress((void**)&wilo, g_wilo);
    cudaGetSymbolAddress((void**)&wohi, g_wohi);
    cudaGetSymbolAddress((void**)&wolo, g_wolo);
    cudaGetSymbolAddress((void**)&yhi,  g_yhi);
    cudaGetSymbolAddress((void**)&ylo,  g_ylo);

    cudaFuncSetAttribute(gemm_bf16x3_kernel<true>,
                         cudaFuncAttributeMaxDynamicSharedMemorySize, TC_SMEM);
    cudaFuncSetAttribute(gemm_bf16x3_kernel<false>,
                         cudaFuncAttributeMaxDynamicSharedMemorySize, TC_SMEM);

    // hi/lo splits for GEMM1 operands + out_w
    {
        const int n1 = kRows * kDM;        // x: 2M
        const int n2 = 2 * kDI * kDM;      // in_w: 4.19M
        const int n3 = kDM * kDI;          // out_w: 2.1M
        cvt_hilo_kernel<<<(n1 + 255) / 256, 256>>>(x, xhi, xlo, n1);
        cvt_hilo_kernel<<<(n2 + 255) / 256, 256>>>(in_w, wihi, wilo, n2);
        cvt_hilo_kernel<<<(n3 + 255) / 256, 256>>>(out_w, wohi, wolo, n3);
    }

    // GEMM1: xz = x @ in_w^T + in_b   (M=2048, N=4096, K=1024)
    {
        dim3 grid((2 * kDI) / 128, kRows / 128);
        gemm_bf16x3_kernel<true><<<grid, 256, TC_SMEM>>>(
            xhi, xlo, wihi, wilo, in_b, xz_p, kDM, 2 * kDI);
    }
    // conv + SiLU gate
    conv_gate_kernel<<<(kRows * kDI) / 256, 256>>>(conv_w, conv_b);
    // xproj
    proj_kernel<<<kRows, 256>>>(xproj_w);
    // chunked selective scan (pass3 emits y as bf16 hi/lo)
    {
        const int grid_scan = kB * kNCH * (kDI / 256);   // 512
        scan_pass1_kernel<<<grid_scan, 256>>>(dt_w, dt_b, A_log);
        scan_combine_kernel<<<(kB * kDI * kDS) / 256, 256>>>();
        scan_pass3_kernel<<<grid_scan, 256>>>(dt_w, dt_b, A_log, Dv);
    }
    // GEMM2: out = y @ out_w^T  (M=2048, N=1024, K=2048)
    {
        dim3 grid(kDM / 128, kRows / 128);
        gemm_bf16x3_kernel<false><<<grid, 256, TC_SMEM>>>(
            yhi, ylo, wohi, wolo, nullptr, out, kDI, kDM);
    }
}

// round 8
// speedup vs baseline: 3.1773x; 1.1779x over previous
#include <cuda_runtime.h>
#include <cuda_bf16.h>
#include <cstdint>
#include <cstddef>

// ---------------------------------------------------------------------------
// MambaBlock: b=2, L=1024, d_model=1024, d_inner=2048, d_state=16, d_conv=4
// bf16x3 mma.sync GEMMs (swizzled smem, 2 CTA/SM) + conv/gate + xproj + scan
// ---------------------------------------------------------------------------

namespace {
constexpr int kDI   = 2048;
constexpr int kDS   = 16;
constexpr int kL    = 1024;
constexpr int kB    = 2;
constexpr int kDM   = 1024;
constexpr int kRows = kB * kL;        // 2048
constexpr int kNP   = 2 * kDS + 1;    // 33
constexpr int kNCH  = 32;             // scan chunks
constexpr int kTCH  = kL / kNCH;      // 32

// GEMM smem: 4 matrices (Ahi,Alo,Bhi,Blo), 128 rows x 32 bf16 (64B), swizzled
constexpr int MATB   = 128 * 64;              // 8192
constexpr int STAGEB = 4 * MATB;              // 32768
constexpr int STAGES = 3;
constexpr int TC_SMEM = STAGES * STAGEB;      // 98304 -> 2 CTAs/SM
}

// Scratch (allocation-free rule: device globals)
__device__ float g_xz[(size_t)kRows * 2 * kDI];
__device__ float g_xh[(size_t)kRows * kDI];
__device__ float g_proj[(size_t)kRows * kNP];
__device__ float g_aprod [(size_t)kB * kNCH * kDI * kDS];
__device__ float g_hloc  [(size_t)kB * kNCH * kDI * kDS];
__device__ float g_hstart[(size_t)kB * kNCH * kDI * kDS];
__device__ unsigned short g_xhi [(size_t)kRows * kDM];
__device__ unsigned short g_xlo [(size_t)kRows * kDM];
__device__ unsigned short g_wihi[(size_t)2 * kDI * kDM];
__device__ unsigned short g_wilo[(size_t)2 * kDI * kDM];
__device__ unsigned short g_wohi[(size_t)kDM * kDI];
__device__ unsigned short g_wolo[(size_t)kDM * kDI];
__device__ unsigned short g_yhi [(size_t)kRows * kDI];
__device__ unsigned short g_ylo [(size_t)kRows * kDI];

// ---------------------------------------------------------------------------
// PTX helpers
// ---------------------------------------------------------------------------
__device__ __forceinline__ uint32_t smem_u32(const void* p) {
    uint32_t a;
    asm("{ .reg .u64 t; cvta.to.shared.u64 t, %1; cvt.u32.u64 %0, t; }" : "=r"(a) : "l"(p));
    return a;
}
__device__ __forceinline__ void cp16(uint32_t saddr, const void* gaddr) {
    asm volatile("cp.async.cg.shared.global [%0], [%1], 16;" :: "r"(saddr), "l"(gaddr));
}
__device__ __forceinline__ void ldsm_x4(uint32_t a, uint32_t r[4]) {
    asm volatile("ldmatrix.sync.aligned.m8n8.x4.shared.b16 {%0,%1,%2,%3}, [%4];"
                 : "=r"(r[0]), "=r"(r[1]), "=r"(r[2]), "=r"(r[3]) : "r"(a));
}
__device__ __forceinline__ void ldsm_x2(uint32_t a, uint32_t r[2]) {
    asm volatile("ldmatrix.sync.aligned.m8n8.x2.shared.b16 {%0,%1}, [%2];"
                 : "=r"(r[0]), "=r"(r[1]) : "r"(a));
}
__device__ __forceinline__ void mma_bf16(float c[4], const uint32_t a[4], const uint32_t b[2]) {
    asm volatile(
        "mma.sync.aligned.m16n8k16.row.col.f32.bf16.bf16.f32 "
        "{%0,%1,%2,%3}, {%4,%5,%6,%7}, {%8,%9}, {%0,%1,%2,%3};"
        : "+f"(c[0]), "+f"(c[1]), "+f"(c[2]), "+f"(c[3])
        : "r"(a[0]), "r"(a[1]), "r"(a[2]), "r"(a[3]), "r"(b[0]), "r"(b[1]));
}
// swizzled offset within one 128x64B matrix: row r, 16B chunk c (0..3)
__device__ __forceinline__ uint32_t swz(uint32_t r, uint32_t c) {
    return r * 64u + ((c ^ ((r >> 1) & 3u)) << 4);
}

// ---------------------------------------------------------------------------
// float -> (bf16 hi, bf16 lo) split
// ---------------------------------------------------------------------------
__global__ void __launch_bounds__(256)
cvt_hilo_kernel(const float* __restrict__ in, unsigned short* __restrict__ hi,
                unsigned short* __restrict__ lo, int n)
{
    const int i = blockIdx.x * 256 + threadIdx.x;
    if (i >= n) return;
    const float x = in[i];
    const __nv_bfloat16 h = __float2bfloat16(x);
    hi[i] = __bfloat16_as_ushort(h);
    lo[i] = __bfloat16_as_ushort(__float2bfloat16(x - __bfloat162float(h)));
}

// ---------------------------------------------------------------------------
// bf16x3 NT GEMM: C[m,n] = sum_k A[m,k]*B[n,k] (+bias[n])
// 128x128 CTA tile, 8 warps x (64x32), BK=32, 3-stage cp.async, swizzled smem.
// ---------------------------------------------------------------------------
template <bool BIAS>
__global__ void __launch_bounds__(256, 2)
gemm_bf16x3_kernel(const unsigned short* __restrict__ Ahi,
                   const unsigned short* __restrict__ Alo,
                   const unsigned short* __restrict__ Bhi,
                   const unsigned short* __restrict__ Blo,
                   const float* __restrict__ bias, float* __restrict__ C,
                   int K, int N)
{
    extern __shared__ char sm[];
    const uint32_t sbase = smem_u32(sm);
    const int tid  = threadIdx.x;
    const int wid  = tid >> 5;
    const int lane = tid & 31;
    const int m0 = blockIdx.y * 128;
    const int n0 = blockIdx.x * 128;
    const int wm = wid & 1;          // 2 row bands of 64
    const int wn = wid >> 1;         // 4 col bands of 32

    const unsigned short* mats[4] = {
        Ahi + (size_t)m0 * K, Alo + (size_t)m0 * K,
        Bhi + (size_t)n0 * K, Blo + (size_t)n0 * K };

    const int NK = K >> 5;

    // cp.async loader: thread t covers matrix (t>>6): 8 x 16B chunks
    const int lm = tid >> 6;
    const int lt = tid & 63;
    const unsigned short* gmat = mats[lm];

    auto issue_stage = [&](int kc) {
        const uint32_t sb = sbase + (uint32_t)(kc % STAGES) * STAGEB + lm * MATB;
        const char* gb = (const char*)(gmat) + (size_t)kc * 64;
#pragma unroll
        for (int j = 0; j < 8; j++) {
            const int id  = lt + j * 64;       // 0..511
            const uint32_t row = id >> 2;
            const uint32_t c16 = id & 3;
            cp16(sb + swz(row, c16), gb + (size_t)row * K * 2 + c16 * 16);
        }
    };

    issue_stage(0);
    asm volatile("cp.async.commit_group;");
    issue_stage(1);
    asm volatile("cp.async.commit_group;");

    float acc[4][4][4];
#pragma unroll
    for (int mt = 0; mt < 4; mt++)
#pragma unroll
        for (int nt = 0; nt < 4; nt++)
#pragma unroll
            for (int r = 0; r < 4; r++) acc[mt][nt][r] = 0.0f;

    // lane-derived fragment rows / chunk indices
    const int ag = lane >> 3;                         // 0..3
    const uint32_t arow = (ag & 1) * 8 + (lane & 7);  // row within 16 (A)
    const uint32_t ac0  = (uint32_t)(ag >> 1);        // A chunk base (0/1)
    const uint32_t brow = lane & 7;                   // row within 8 (B)
    const uint32_t bc0  = (uint32_t)((lane >> 3) & 1);

    for (int kc = 0; kc < NK; kc++) {
        asm volatile("cp.async.wait_group 1;");
        __syncthreads();
        if (kc + 2 < NK) issue_stage(kc + 2);
        asm volatile("cp.async.commit_group;");

        const uint32_t stg = sbase + (uint32_t)(kc % STAGES) * STAGEB;
        const uint32_t bAhi = stg + 0 * MATB;
        const uint32_t bAlo = stg + 1 * MATB;
        const uint32_t bBhi = stg + 2 * MATB;
        const uint32_t bBlo = stg + 3 * MATB;

#pragma unroll
        for (int kh = 0; kh < 2; kh++) {
            const uint32_t ca = ac0 + kh * 2;
            const uint32_t cb = bc0 + kh * 2;
            uint32_t fBh[4][2], fBl[4][2];
#pragma unroll
            for (int nt = 0; nt < 4; nt++) {
                const uint32_t rB = wn * 32 + nt * 8 + brow;
                const uint32_t o = swz(rB, cb);
                ldsm_x2(bBhi + o, fBh[nt]);
                ldsm_x2(bBlo + o, fBl[nt]);
            }
#pragma unroll
            for (int mt = 0; mt < 4; mt++) {
                const uint32_t rA = wm * 64 + mt * 16 + arow;
                const uint32_t o = swz(rA, ca);
                uint32_t fAh[4], fAl[4];
                ldsm_x4(bAhi + o, fAh);
                ldsm_x4(bAlo + o, fAl);
#pragma unroll
                for (int nt = 0; nt < 4; nt++) {
                    mma_bf16(acc[mt][nt], fAh, fBh[nt]);
                    mma_bf16(acc[mt][nt], fAh, fBl[nt]);
                    mma_bf16(acc[mt][nt], fAl, fBh[nt]);
                }
            }
        }
    }

    // Epilogue: direct float2 stores
    const int gid = lane >> 2;
    const int tig = lane & 3;
#pragma unroll
    for (int mt = 0; mt < 4; mt++) {
        const int r0 = m0 + wm * 64 + mt * 16 + gid;
#pragma unroll
        for (int nt = 0; nt < 4; nt++) {
            const int c = n0 + wn * 32 + nt * 8 + 2 * tig;
            float b0 = 0.0f, b1 = 0.0f;
            if (BIAS) { b0 = bias[c]; b1 = bias[c + 1]; }
            float2 v0 = make_float2(acc[mt][nt][0] + b0, acc[mt][nt][1] + b1);
            float2 v1 = make_float2(acc[mt][nt][2] + b0, acc[mt][nt][3] + b1);
            *(float2*)(&C[(size_t)r0 * N + c])       = v0;
            *(float2*)(&C[(size_t)(r0 + 8) * N + c]) = v1;
        }
    }
}

// ---------------------------------------------------------------------------
// Depthwise causal conv (D_CONV=4) + bias + SiLU(z) gate.
// ---------------------------------------------------------------------------
__global__ void __launch_bounds__(256)
conv_gate_kernel(const float* __restrict__ conv_w,
                 const float* __restrict__ conv_b)
{
    const int idx = blockIdx.x * 256 + threadIdx.x;
    const int i = idx & (kDI - 1);
    const int t = (idx >> 11) & (kL - 1);
    const int b = idx >> 21;

    const float* base = g_xz + (size_t)b * kL * (2 * kDI) + i;
    float accv = conv_b[i];
#pragma unroll
    for (int k = 0; k < 4; k++) {
        const int tt = t + k - 3;
        if (tt >= 0) accv += conv_w[i * 4 + k] * base[(size_t)tt * (2 * kDI)];
    }
    const float z = g_xz[((size_t)(b * kL + t)) * (2 * kDI) + kDI + i];
    const float sig = 1.0f / (1.0f + __expf(-z));
    g_xh[idx] = accv * (z * sig);
}

// ---------------------------------------------------------------------------
// proj = xh @ xproj_w^T
// ---------------------------------------------------------------------------
__global__ void __launch_bounds__(256)
proj_kernel(const float* __restrict__ w)
{
    const int row = blockIdx.x;
    const float* xr = g_xh + (size_t)row * kDI;

    float acc[kNP];
#pragma unroll
    for (int n = 0; n < kNP; n++) acc[n] = 0.0f;

    for (int k = threadIdx.x; k < kDI; k += 256) {
        const float xv = xr[k];
#pragma unroll
        for (int n = 0; n < kNP; n++) acc[n] += xv * w[n * kDI + k];
    }

#pragma unroll
    for (int n = 0; n < kNP; n++) {
#pragma unroll
        for (int off = 16; off > 0; off >>= 1)
            acc[n] += __shfl_xor_sync(0xFFFFFFFFu, acc[n], off);
    }

    __shared__ float red[kNP][8];
    const int warp = threadIdx.x >> 5;
    const int lane = threadIdx.x & 31;
    if (lane == 0) {
#pragma unroll
        for (int n = 0; n < kNP; n++) red[n][warp] = acc[n];
    }
    __syncthreads();
    if (threadIdx.x < kNP) {
        float s = 0.0f;
#pragma unroll
        for (int w8 = 0; w8 < 8; w8++) s += red[threadIdx.x][w8];
        g_proj[(size_t)row * kNP + threadIdx.x] = s;
    }
}

// ---------------------------------------------------------------------------
// Chunked selective scan. delta = exp(softplus(.)) = 1 + exp(.) identity.
// ---------------------------------------------------------------------------
__global__ void __launch_bounds__(256)
scan_pass1_kernel(const float* __restrict__ dt_w,
                  const float* __restrict__ dt_b,
                  const float* __restrict__ A_log)
{
    const int gi = blockIdx.x;
    const int b = gi / (kNCH * (kDI / 256));
    const int c = (gi / (kDI / 256)) % kNCH;
    const int i = (gi % (kDI / 256)) * 256 + threadIdx.x;

    float Arow[kDS], h[kDS], P[kDS];
#pragma unroll
    for (int s = 0; s < kDS; s++) {
        Arow[s] = -__expf(A_log[i * kDS + s]);
        h[s] = 0.0f;
        P[s] = 1.0f;
    }
    const float dtw = dt_w[i];
    const float dtb = dt_b[i];

    __shared__ float sp[kTCH * kNP];
    {
        const size_t base = (size_t)(b * kL + c * kTCH) * kNP;
        for (int idx = threadIdx.x; idx < kTCH * kNP; idx += 256)
            sp[idx] = g_proj[base + idx];
    }
    __syncthreads();

    for (int tt = 0; tt < kTCH; tt++) {
        const int t = c * kTCH + tt;
        const float* row = sp + tt * kNP;
        const float xt = g_xh[((size_t)(b * kL + t)) * kDI + i];
        const float delta = 1.0f + __expf(row[0] * dtw + dtb);
        const float dx = delta * xt;
#pragma unroll
        for (int s = 0; s < kDS; s++) {
            const float a = __expf(Arow[s] * delta);
            h[s] = a * h[s] + row[1 + s] * dx;
            P[s] *= a;
        }
    }

    const size_t o = (((size_t)(b * kNCH + c)) * kDI + i) * kDS;
#pragma unroll
    for (int v = 0; v < kDS / 4; v++) {
        *(float4*)(g_aprod + o + v * 4) = make_float4(P[v*4], P[v*4+1], P[v*4+2], P[v*4+3]);
        *(float4*)(g_hloc  + o + v * 4) = make_float4(h[v*4], h[v*4+1], h[v*4+2], h[v*4+3]);
    }
}

__global__ void __launch_bounds__(256)
scan_combine_kernel()
{
    const int idx = blockIdx.x * 256 + threadIdx.x;
    const int b = idx >> 15;
    const int rem = idx & ((kDI * kDS) - 1);
    float h = 0.0f;
#pragma unroll 4
    for (int c = 0; c < kNCH; c++) {
        const size_t o = ((size_t)(b * kNCH + c)) * (kDI * kDS) + rem;
        g_hstart[o] = h;
        h = g_aprod[o] * h + g_hloc[o];
    }
}

__global__ void __launch_bounds__(256)
scan_pass3_kernel(const float* __restrict__ dt_w,
                  const float* __restrict__ dt_b,
                  const float* __restrict__ A_log,
                  const float* __restrict__ Dv)
{
    const int gi = blockIdx.x;
    const int b = gi / (kNCH * (kDI / 256));
    const int c = (gi / (kDI / 256)) % kNCH;
    const int i = (gi % (kDI / 256)) * 256 + threadIdx.x;

    float Arow[kDS], h[kDS];
    {
        const size_t o = (((size_t)(b * kNCH + c)) * kDI + i) * kDS;
#pragma unroll
        for (int v = 0; v < kDS / 4; v++) {
            float4 hv = *(const float4*)(g_hstart + o + v * 4);
            h[v*4] = hv.x; h[v*4+1] = hv.y; h[v*4+2] = hv.z; h[v*4+3] = hv.w;
        }
    }
#pragma unroll
    for (int s = 0; s < kDS; s++)
        Arow[s] = -__expf(A_log[i * kDS + s]);

    const float dtw = dt_w[i];
    const float dtb = dt_b[i];
    const float Di  = Dv[i];

    __shared__ float sp[kTCH * kNP];
    {
        const size_t base = (size_t)(b * kL + c * kTCH) * kNP;
        for (int idx = threadIdx.x; idx < kTCH * kNP; idx += 256)
            sp[idx] = g_proj[base + idx];
    }
    __syncthreads();

    for (int tt = 0; tt < kTCH; tt++) {
        const int t = c * kTCH + tt;
        const float* row = sp + tt * kNP;
        const size_t oy = ((size_t)(b * kL + t)) * kDI + i;
        const float xt = g_xh[oy];
        const float delta = 1.0f + __expf(row[0] * dtw + dtb);
        const float dx = delta * xt;
        float yv = 0.0f;
#pragma unroll
        for (int s = 0; s < kDS; s++) {
            const float a = __expf(Arow[s] * delta);
            h[s] = a * h[s] + row[1 + s] * dx;
            yv += h[s] * row[1 + kDS + s];
        }
        const float yf = yv + Di * xt;
        const __nv_bfloat16 hy = __float2bfloat16(yf);
        g_yhi[oy] = __bfloat16_as_ushort(hy);
        g_ylo[oy] = __bfloat16_as_ushort(__float2bfloat16(yf - __bfloat162float(hy)));
    }
}

// ---------------------------------------------------------------------------
// Launch
// ---------------------------------------------------------------------------
extern "C" void kernel_launch(void* const* d_in, const int* in_sizes, int n_in,
                              void* d_out, int out_size)
{
    const float* x       = (const float*)d_in[0];
    const float* in_w    = (const float*)d_in[1];
    const float* in_b    = (const float*)d_in[2];
    const float* conv_w  = (const float*)d_in[3];
    const float* conv_b  = (const float*)d_in[4];
    const float* xproj_w = (const float*)d_in[5];
    const float* dt_w    = (const float*)d_in[6];
    const float* dt_b    = (const float*)d_in[7];
    const float* A_log   = (const float*)d_in[8];
    const float* Dv      = (const float*)d_in[9];
    const float* out_w   = (const float*)d_in[10];
    float* out = (float*)d_out;

    float* xz_p;
    unsigned short *xhi, *xlo, *wihi, *wilo, *wohi, *wolo, *yhi, *ylo;
    cudaGetSymbolAddress((void**)&xz_p, g_xz);
    cudaGetSymbolAddress((void**)&xhi,  g_xhi);
    cudaGetSymbolAddress((void**)&xlo,  g_xlo);
    cudaGetSymbolAddress((void**)&wihi, g_wihi);
    cudaGetSymbolAddress((void**)&wilo, g_wilo);
    cudaGetSymbolAddress((void**)&wohi, g_wohi);
    cudaGetSymbolAddress((void**)&wolo, g_wolo);
    cudaGetSymbolAddress((void**)&yhi,  g_yhi);
    cudaGetSymbolAddress((void**)&ylo,  g_ylo);

    cudaFuncSetAttribute(gemm_bf16x3_kernel<true>,
                         cudaFuncAttributeMaxDynamicSharedMemorySize, TC_SMEM);
    cudaFuncSetAttribute(gemm_bf16x3_kernel<false>,
                         cudaFuncAttributeMaxDynamicSharedMemorySize, TC_SMEM);

    // hi/lo splits for GEMM operands
    {
        const int n1 = kRows * kDM;
        const int n2 = 2 * kDI * kDM;
        const int n3 = kDM * kDI;
        cvt_hilo_kernel<<<(n1 + 255) / 256, 256>>>(x, xhi, xlo, n1);
        cvt_hilo_kernel<<<(n2 + 255) / 256, 256>>>(in_w, wihi, wilo, n2);
        cvt_hilo_kernel<<<(n3 + 255) / 256, 256>>>(out_w, wohi, wolo, n3);
    }

    // GEMM1: xz = x @ in_w^T + in_b   (M=2048, N=4096, K=1024)
    {
        dim3 grid((2 * kDI) / 128, kRows / 128);
        gemm_bf16x3_kernel<true><<<grid, 256, TC_SMEM>>>(
            xhi, xlo, wihi, wilo, in_b, xz_p, kDM, 2 * kDI);
    }
    // conv + SiLU gate
    conv_gate_kernel<<<(kRows * kDI) / 256, 256>>>(conv_w, conv_b);
    // xproj
    proj_kernel<<<kRows, 256>>>(xproj_w);
    // chunked selective scan (pass3 emits y as bf16 hi/lo)
    {
        const int grid_scan = kB * kNCH * (kDI / 256);   // 512
        scan_pass1_kernel<<<grid_scan, 256>>>(dt_w, dt_b, A_log);
        scan_combine_kernel<<<(kB * kDI * kDS) / 256, 256>>>();
        scan_pass3_kernel<<<grid_scan, 256>>>(dt_w, dt_b, A_log, Dv);
    }
    // GEMM2: out = y @ out_w^T  (M=2048, N=1024, K=2048)
    {
        dim3 grid(kDM / 128, kRows / 128);
        gemm_bf16x3_kernel<false><<<grid, 256, TC_SMEM>>>(
            yhi, ylo, wohi, wolo, nullptr, out, kDI, kDM);
    }
}

// round 9
// speedup vs baseline: 3.1798x; 1.0008x over previous
#include <cuda_runtime.h>
#include <cuda_bf16.h>
#include <cstdint>
#include <cstddef>

// ---------------------------------------------------------------------------
// MambaBlock: b=2, L=1024, d_model=1024, d_inner=2048, d_state=16, d_conv=4
// bf16x3 mma.sync GEMMs (swizzled smem, 2 CTA/SM, split-K GEMM2)
// + conv/gate + tiled xproj + chunked selective scan
// ---------------------------------------------------------------------------

namespace {
constexpr int kDI   = 2048;
constexpr int kDS   = 16;
constexpr int kL    = 1024;
constexpr int kB    = 2;
constexpr int kDM   = 1024;
constexpr int kRows = kB * kL;        // 2048
constexpr int kNP   = 2 * kDS + 1;    // 33
constexpr int kNCH  = 64;             // scan chunks
constexpr int kTCH  = kL / kNCH;      // 16

constexpr int MATB   = 128 * 64;              // 8192 (128 rows x 64B)
constexpr int STAGEB = 4 * MATB;              // 32768
constexpr int STAGES = 3;
constexpr int TC_SMEM = STAGES * STAGEB;      // 98304 -> 2 CTAs/SM
}

// Scratch (allocation-free rule: device globals)
__device__ float g_xz[(size_t)kRows * 2 * kDI];
__device__ float g_xh[(size_t)kRows * kDI];
__device__ float g_proj[(size_t)kRows * kNP];
__device__ float g_part[(size_t)kRows * kDM];
__device__ float g_aprod [(size_t)kB * kNCH * kDI * kDS];
__device__ float g_hloc  [(size_t)kB * kNCH * kDI * kDS];
__device__ float g_hstart[(size_t)kB * kNCH * kDI * kDS];
__device__ unsigned short g_xhi [(size_t)kRows * kDM];
__device__ unsigned short g_xlo [(size_t)kRows * kDM];
__device__ unsigned short g_wihi[(size_t)2 * kDI * kDM];
__device__ unsigned short g_wilo[(size_t)2 * kDI * kDM];
__device__ unsigned short g_wohi[(size_t)kDM * kDI];
__device__ unsigned short g_wolo[(size_t)kDM * kDI];
__device__ unsigned short g_yhi [(size_t)kRows * kDI];
__device__ unsigned short g_ylo [(size_t)kRows * kDI];

// ---------------------------------------------------------------------------
// PTX helpers
// ---------------------------------------------------------------------------
__device__ __forceinline__ uint32_t smem_u32(const void* p) {
    uint32_t a;
    asm("{ .reg .u64 t; cvta.to.shared.u64 t, %1; cvt.u32.u64 %0, t; }" : "=r"(a) : "l"(p));
    return a;
}
__device__ __forceinline__ void cp16(uint32_t saddr, const void* gaddr) {
    asm volatile("cp.async.cg.shared.global [%0], [%1], 16;" :: "r"(saddr), "l"(gaddr));
}
__device__ __forceinline__ void ldsm_x4(uint32_t a, uint32_t r[4]) {
    asm volatile("ldmatrix.sync.aligned.m8n8.x4.shared.b16 {%0,%1,%2,%3}, [%4];"
                 : "=r"(r[0]), "=r"(r[1]), "=r"(r[2]), "=r"(r[3]) : "r"(a));
}
__device__ __forceinline__ void ldsm_x2(uint32_t a, uint32_t r[2]) {
    asm volatile("ldmatrix.sync.aligned.m8n8.x2.shared.b16 {%0,%1}, [%2];"
                 : "=r"(r[0]), "=r"(r[1]) : "r"(a));
}
__device__ __forceinline__ void mma_bf16(float c[4], const uint32_t a[4], const uint32_t b[2]) {
    asm volatile(
        "mma.sync.aligned.m16n8k16.row.col.f32.bf16.bf16.f32 "
        "{%0,%1,%2,%3}, {%4,%5,%6,%7}, {%8,%9}, {%0,%1,%2,%3};"
        : "+f"(c[0]), "+f"(c[1]), "+f"(c[2]), "+f"(c[3])
        : "r"(a[0]), "r"(a[1]), "r"(a[2]), "r"(a[3]), "r"(b[0]), "r"(b[1]));
}
__device__ __forceinline__ uint32_t swz(uint32_t r, uint32_t c) {
    return r * 64u + ((c ^ ((r >> 1) & 3u)) << 4);
}

// ---------------------------------------------------------------------------
// float -> (bf16 hi, bf16 lo) split: 3 arrays in one launch
// ---------------------------------------------------------------------------
__global__ void __launch_bounds__(256)
cvt3_kernel(const float* __restrict__ a, unsigned short* __restrict__ ahi,
            unsigned short* __restrict__ alo, int na,
            const float* __restrict__ b, unsigned short* __restrict__ bhi,
            unsigned short* __restrict__ blo, int nb,
            const float* __restrict__ c, unsigned short* __restrict__ chi,
            unsigned short* __restrict__ clo, int nc)
{
    int i = blockIdx.x * 256 + threadIdx.x;
    const float* in; unsigned short *hi, *lo;
    if (i < na) { in = a; hi = ahi; lo = alo; }
    else if (i < na + nb) { i -= na; in = b; hi = bhi; lo = blo; }
    else { i -= na + nb; if (i >= nc) return; in = c; hi = chi; lo = clo; }
    const float x = in[i];
    const __nv_bfloat16 h = __float2bfloat16(x);
    hi[i] = __bfloat16_as_ushort(h);
    lo[i] = __bfloat16_as_ushort(__float2bfloat16(x - __bfloat162float(h)));
}

// ---------------------------------------------------------------------------
// bf16x3 NT GEMM: C[m,n] = sum_{k in [z*KL,(z+1)*KL)} A[m,k]*B[n,k] (+bias[n])
// z = blockIdx.z; z==0 writes C, z==1 writes Cpart.
// ---------------------------------------------------------------------------
template <bool BIAS>
__global__ void __launch_bounds__(256, 2)
gemm_bf16x3_kernel(const unsigned short* __restrict__ Ahi,
                   const unsigned short* __restrict__ Alo,
                   const unsigned short* __restrict__ Bhi,
                   const unsigned short* __restrict__ Blo,
                   const float* __restrict__ bias, float* __restrict__ C,
                   float* __restrict__ Cpart, int K, int KL, int N)
{
    extern __shared__ char sm[];
    const uint32_t sbase = smem_u32(sm);
    const int tid  = threadIdx.x;
    const int wid  = tid >> 5;
    const int lane = tid & 31;
    const int m0 = blockIdx.y * 128;
    const int n0 = blockIdx.x * 128;
    const int koff = blockIdx.z * KL;
    const int wm = wid & 1;
    const int wn = wid >> 1;

    const unsigned short* mats[4] = {
        Ahi + (size_t)m0 * K + koff, Alo + (size_t)m0 * K + koff,
        Bhi + (size_t)n0 * K + koff, Blo + (size_t)n0 * K + koff };

    const int NK = KL >> 5;

    const int lm = tid >> 6;
    const int lt = tid & 63;
    const unsigned short* gmat = mats[lm];

    auto issue_stage = [&](int kc) {
        const uint32_t sb = sbase + (uint32_t)(kc % STAGES) * STAGEB + lm * MATB;
        const char* gb = (const char*)(gmat) + (size_t)kc * 64;
#pragma unroll
        for (int j = 0; j < 8; j++) {
            const int id  = lt + j * 64;
            const uint32_t row = id >> 2;
            const uint32_t c16 = id & 3;
            cp16(sb + swz(row, c16), gb + (size_t)row * K * 2 + c16 * 16);
        }
    };

    issue_stage(0);
    asm volatile("cp.async.commit_group;");
    issue_stage(1);
    asm volatile("cp.async.commit_group;");

    float acc[4][4][4];
#pragma unroll
    for (int mt = 0; mt < 4; mt++)
#pragma unroll
        for (int nt = 0; nt < 4; nt++)
#pragma unroll
            for (int r = 0; r < 4; r++) acc[mt][nt][r] = 0.0f;

    const int ag = lane >> 3;
    const uint32_t arow = (ag & 1) * 8 + (lane & 7);
    const uint32_t ac0  = (uint32_t)(ag >> 1);
    const uint32_t brow = lane & 7;
    const uint32_t bc0  = (uint32_t)((lane >> 3) & 1);

    for (int kc = 0; kc < NK; kc++) {
        asm volatile("cp.async.wait_group 1;");
        __syncthreads();
        if (kc + 2 < NK) issue_stage(kc + 2);
        asm volatile("cp.async.commit_group;");

        const uint32_t stg = sbase + (uint32_t)(kc % STAGES) * STAGEB;
        const uint32_t bAhi = stg + 0 * MATB;
        const uint32_t bAlo = stg + 1 * MATB;
        const uint32_t bBhi = stg + 2 * MATB;
        const uint32_t bBlo = stg + 3 * MATB;

#pragma unroll
        for (int kh = 0; kh < 2; kh++) {
            const uint32_t ca = ac0 + kh * 2;
            const uint32_t cb = bc0 + kh * 2;
            uint32_t fBh[4][2], fBl[4][2];
#pragma unroll
            for (int nt = 0; nt < 4; nt++) {
                const uint32_t rB = wn * 32 + nt * 8 + brow;
                const uint32_t o = swz(rB, cb);
                ldsm_x2(bBhi + o, fBh[nt]);
                ldsm_x2(bBlo + o, fBl[nt]);
            }
#pragma unroll
            for (int mt = 0; mt < 4; mt++) {
                const uint32_t rA = wm * 64 + mt * 16 + arow;
                const uint32_t o = swz(rA, ca);
                uint32_t fAh[4], fAl[4];
                ldsm_x4(bAhi + o, fAh);
                ldsm_x4(bAlo + o, fAl);
#pragma unroll
                for (int nt = 0; nt < 4; nt++) {
                    mma_bf16(acc[mt][nt], fAh, fBh[nt]);
                    mma_bf16(acc[mt][nt], fAh, fBl[nt]);
                    mma_bf16(acc[mt][nt], fAl, fBh[nt]);
                }
            }
        }
    }

    float* Cout = blockIdx.z ? Cpart : C;
    const int gid = lane >> 2;
    const int tig = lane & 3;
#pragma unroll
    for (int mt = 0; mt < 4; mt++) {
        const int r0 = m0 + wm * 64 + mt * 16 + gid;
#pragma unroll
        for (int nt = 0; nt < 4; nt++) {
            const int c = n0 + wn * 32 + nt * 8 + 2 * tig;
            float b0 = 0.0f, b1 = 0.0f;
            if (BIAS) { b0 = bias[c]; b1 = bias[c + 1]; }
            float2 v0 = make_float2(acc[mt][nt][0] + b0, acc[mt][nt][1] + b1);
            float2 v1 = make_float2(acc[mt][nt][2] + b0, acc[mt][nt][3] + b1);
            *(float2*)(&Cout[(size_t)r0 * N + c])       = v0;
            *(float2*)(&Cout[(size_t)(r0 + 8) * N + c]) = v1;
        }
    }
}

// out += part
__global__ void __launch_bounds__(256)
add_kernel(float* __restrict__ out, const float* __restrict__ part, int n)
{
    const int i = blockIdx.x * 256 + threadIdx.x;
    if (i < n) out[i] += part[i];
}

// ---------------------------------------------------------------------------
// Depthwise causal conv (D_CONV=4) + bias + SiLU(z) gate.
// ---------------------------------------------------------------------------
__global__ void __launch_bounds__(256)
conv_gate_kernel(const float* __restrict__ conv_w,
                 const float* __restrict__ conv_b)
{
    const int idx = blockIdx.x * 256 + threadIdx.x;
    const int i = idx & (kDI - 1);
    const int t = (idx >> 11) & (kL - 1);
    const int b = idx >> 21;

    const float* base = g_xz + (size_t)b * kL * (2 * kDI) + i;
    float accv = conv_b[i];
#pragma unroll
    for (int k = 0; k < 4; k++) {
        const int tt = t + k - 3;
        if (tt >= 0) accv += conv_w[i * 4 + k] * base[(size_t)tt * (2 * kDI)];
    }
    const float z = g_xz[((size_t)(b * kL + t)) * (2 * kDI) + kDI + i];
    const float sig = 1.0f / (1.0f + __expf(-z));
    g_xh[idx] = accv * (z * sig);
}

// ---------------------------------------------------------------------------
// proj = xh @ xproj_w^T, tiled: 16 rows/block, w staged in smem.
// ---------------------------------------------------------------------------
__global__ void __launch_bounds__(256)
proj_kernel(const float* __restrict__ w)
{
    constexpr int KC = 256;
    __shared__ float ws[kNP][KC];

    const int warp = threadIdx.x >> 5;
    const int lane = threadIdx.x & 31;
    const int r0 = blockIdx.x * 16 + warp * 2;

    float acc0[kNP], acc1[kNP];
#pragma unroll
    for (int n = 0; n < kNP; n++) { acc0[n] = 0.0f; acc1[n] = 0.0f; }

    for (int k0 = 0; k0 < kDI; k0 += KC) {
        __syncthreads();
        for (int idx = threadIdx.x; idx < kNP * KC; idx += 256)
            ws[idx >> 8][idx & (KC - 1)] = w[(idx >> 8) * kDI + k0 + (idx & (KC - 1))];
        __syncthreads();

        const float* x0 = g_xh + (size_t)r0 * kDI + k0;
        const float* x1 = x0 + kDI;
#pragma unroll
        for (int j = 0; j < KC / 32; j++) {
            const int kk = lane + 32 * j;
            const float xv0 = x0[kk];
            const float xv1 = x1[kk];
#pragma unroll
            for (int n = 0; n < kNP; n++) {
                const float wv = ws[n][kk];
                acc0[n] += xv0 * wv;
                acc1[n] += xv1 * wv;
            }
        }
    }

#pragma unroll
    for (int n = 0; n < kNP; n++) {
#pragma unroll
        for (int off = 16; off > 0; off >>= 1) {
            acc0[n] += __shfl_xor_sync(0xFFFFFFFFu, acc0[n], off);
            acc1[n] += __shfl_xor_sync(0xFFFFFFFFu, acc1[n], off);
        }
    }
    if (lane == 0) {
#pragma unroll
        for (int n = 0; n < kNP; n++) {
            g_proj[(size_t)r0 * kNP + n]       = acc0[n];
            g_proj[(size_t)(r0 + 1) * kNP + n] = acc1[n];
        }
    }
}

// ---------------------------------------------------------------------------
// Chunked selective scan. delta = exp(softplus(.)) = 1 + exp(.) identity.
// a = exp2(Arow2 * delta), Arow2 = -exp(A_log)*log2(e).
// ---------------------------------------------------------------------------
__global__ void __launch_bounds__(256)
scan_pass1_kernel(const float* __restrict__ dt_w,
                  const float* __restrict__ dt_b,
                  const float* __restrict__ A_log)
{
    const int gi = blockIdx.x;
    const int b = gi / (kNCH * (kDI / 256));
    const int c = (gi / (kDI / 256)) % kNCH;
    const int i = (gi % (kDI / 256)) * 256 + threadIdx.x;

    constexpr float kLog2e = 1.4426950408889634f;
    float Arow[kDS], h[kDS], P[kDS];
#pragma unroll
    for (int s = 0; s < kDS; s++) {
        Arow[s] = -__expf(A_log[i * kDS + s]) * kLog2e;
        h[s] = 0.0f;
        P[s] = 1.0f;
    }
    const float dtw = dt_w[i];
    const float dtb = dt_b[i];

    __shared__ float sp[kTCH * kNP];
    {
        const size_t base = (size_t)(b * kL + c * kTCH) * kNP;
        for (int idx = threadIdx.x; idx < kTCH * kNP; idx += 256)
            sp[idx] = g_proj[base + idx];
    }
    __syncthreads();

    for (int tt = 0; tt < kTCH; tt++) {
        const int t = c * kTCH + tt;
        const float* row = sp + tt * kNP;
        const float xt = g_xh[((size_t)(b * kL + t)) * kDI + i];
        const float delta = 1.0f + __expf(row[0] * dtw + dtb);
        const float dx = delta * xt;
#pragma unroll
        for (int s = 0; s < kDS; s++) {
            const float a = exp2f(Arow[s] * delta);
            h[s] = a * h[s] + row[1 + s] * dx;
            P[s] *= a;
        }
    }

    const size_t o = (((size_t)(b * kNCH + c)) * kDI + i) * kDS;
#pragma unroll
    for (int v = 0; v < kDS / 4; v++) {
        *(float4*)(g_aprod + o + v * 4) = make_float4(P[v*4], P[v*4+1], P[v*4+2], P[v*4+3]);
        *(float4*)(g_hloc  + o + v * 4) = make_float4(h[v*4], h[v*4+1], h[v*4+2], h[v*4+3]);
    }
}

__global__ void __launch_bounds__(256)
scan_combine_kernel()
{
    const int idx = blockIdx.x * 256 + threadIdx.x;
    const int b = idx >> 15;
    const int rem = idx & ((kDI * kDS) - 1);
    float h = 0.0f;
#pragma unroll 4
    for (int c = 0; c < kNCH; c++) {
        const size_t o = ((size_t)(b * kNCH + c)) * (kDI * kDS) + rem;
        g_hstart[o] = h;
        h = g_aprod[o] * h + g_hloc[o];
    }
}

__global__ void __launch_bounds__(256)
scan_pass3_kernel(const float* __restrict__ dt_w,
                  const float* __restrict__ dt_b,
                  const float* __restrict__ A_log,
                  const float* __restrict__ Dv)
{
    const int gi = blockIdx.x;
    const int b = gi / (kNCH * (kDI / 256));
    const int c = (gi / (kDI / 256)) % kNCH;
    const int i = (gi % (kDI / 256)) * 256 + threadIdx.x;

    constexpr float kLog2e = 1.4426950408889634f;
    float Arow[kDS], h[kDS];
    {
        const size_t o = (((size_t)(b * kNCH + c)) * kDI + i) * kDS;
#pragma unroll
        for (int v = 0; v < kDS / 4; v++) {
            float4 hv = *(const float4*)(g_hstart + o + v * 4);
            h[v*4] = hv.x; h[v*4+1] = hv.y; h[v*4+2] = hv.z; h[v*4+3] = hv.w;
        }
    }
#pragma unroll
    for (int s = 0; s < kDS; s++)
        Arow[s] = -__expf(A_log[i * kDS + s]) * kLog2e;

    const float dtw = dt_w[i];
    const float dtb = dt_b[i];
    const float Di  = Dv[i];

    __shared__ float sp[kTCH * kNP];
    {
        const size_t base = (size_t)(b * kL + c * kTCH) * kNP;
        for (int idx = threadIdx.x; idx < kTCH * kNP; idx += 256)
            sp[idx] = g_proj[base + idx];
    }
    __syncthreads();

    for (int tt = 0; tt < kTCH; tt++) {
        const int t = c * kTCH + tt;
        const float* row = sp + tt * kNP;
        const size_t oy = ((size_t)(b * kL + t)) * kDI + i;
        const float xt = g_xh[oy];
        const float delta = 1.0f + __expf(row[0] * dtw + dtb);
        const float dx = delta * xt;
        float yv = 0.0f;
#pragma unroll
        for (int s = 0; s < kDS; s++) {
            const float a = exp2f(Arow[s] * delta);
            h[s] = a * h[s] + row[1 + s] * dx;
            yv += h[s] * row[1 + kDS + s];
        }
        const float yf = yv + Di * xt;
        const __nv_bfloat16 hy = __float2bfloat16(yf);
        g_yhi[oy] = __bfloat16_as_ushort(hy);
        g_ylo[oy] = __bfloat16_as_ushort(__float2bfloat16(yf - __bfloat162float(hy)));
    }
}

// ---------------------------------------------------------------------------
// Launch
// ---------------------------------------------------------------------------
extern "C" void kernel_launch(void* const* d_in, const int* in_sizes, int n_in,
                              void* d_out, int out_size)
{
    const float* x       = (const float*)d_in[0];
    const float* in_w    = (const float*)d_in[1];
    const float* in_b    = (const float*)d_in[2];
    const float* conv_w  = (const float*)d_in[3];
    const float* conv_b  = (const float*)d_in[4];
    const float* xproj_w = (const float*)d_in[5];
    const float* dt_w    = (const float*)d_in[6];
    const float* dt_b    = (const float*)d_in[7];
    const float* A_log   = (const float*)d_in[8];
    const float* Dv      = (const float*)d_in[9];
    const float* out_w   = (const float*)d_in[10];
    float* out = (float*)d_out;

    float *xz_p, *part_p;
    unsigned short *xhi, *xlo, *wihi, *wilo, *wohi, *wolo, *yhi, *ylo;
    cudaGetSymbolAddress((void**)&xz_p,   g_xz);
    cudaGetSymbolAddress((void**)&part_p, g_part);
    cudaGetSymbolAddress((void**)&xhi,  g_xhi);
    cudaGetSymbolAddress((void**)&xlo,  g_xlo);
    cudaGetSymbolAddress((void**)&wihi, g_wihi);
    cudaGetSymbolAddress((void**)&wilo, g_wilo);
    cudaGetSymbolAddress((void**)&wohi, g_wohi);
    cudaGetSymbolAddress((void**)&wolo, g_wolo);
    cudaGetSymbolAddress((void**)&yhi,  g_yhi);
    cudaGetSymbolAddress((void**)&ylo,  g_ylo);

    cudaFuncSetAttribute(gemm_bf16x3_kernel<true>,
                         cudaFuncAttributeMaxDynamicSharedMemorySize, TC_SMEM);
    cudaFuncSetAttribute(gemm_bf16x3_kernel<false>,
                         cudaFuncAttributeMaxDynamicSharedMemorySize, TC_SMEM);

    // hi/lo splits (one launch)
    {
        const int n1 = kRows * kDM;        // x
        const int n2 = 2 * kDI * kDM;      // in_w
        const int n3 = kDM * kDI;          // out_w
        const int tot = n1 + n2 + n3;
        cvt3_kernel<<<(tot + 255) / 256, 256>>>(x, xhi, xlo, n1,
                                                in_w, wihi, wilo, n2,
                                                out_w, wohi, wolo, n3);
    }

    // GEMM1: xz = x @ in_w^T + in_b   (M=2048, N=4096, K=1024)
    {
        dim3 grid((2 * kDI) / 128, kRows / 128, 1);
        gemm_bf16x3_kernel<true><<<grid, 256, TC_SMEM>>>(
            xhi, xlo, wihi, wilo, in_b, xz_p, nullptr, kDM, kDM, 2 * kDI);
    }
    // conv + SiLU gate
    conv_gate_kernel<<<(kRows * kDI) / 256, 256>>>(conv_w, conv_b);
    // xproj (tiled, 16 rows/block)
    proj_kernel<<<kRows / 16, 256>>>(xproj_w);
    // chunked selective scan (pass3 emits y as bf16 hi/lo)
    {
        const int grid_scan = kB * kNCH * (kDI / 256);   // 1024
        scan_pass1_kernel<<<grid_scan, 256>>>(dt_w, dt_b, A_log);
        scan_combine_kernel<<<(kB * kDI * kDS) / 256, 256>>>();
        scan_pass3_kernel<<<grid_scan, 256>>>(dt_w, dt_b, A_log, Dv);
    }
    // GEMM2: out = y @ out_w^T  (M=2048, N=1024, K=2048), split-K=2
    {
        dim3 grid(kDM / 128, kRows / 128, 2);
        gemm_bf16x3_kernel<false><<<grid, 256, TC_SMEM>>>(
            yhi, ylo, wohi, wolo, nullptr, out, part_p, kDI, kDI / 2, kDM);
        add_kernel<<<(kRows * kDM) / 256, 256>>>(out, part_p, kRows * kDM);
    }
}

// round 12
// speedup vs baseline: 3.3062x; 1.0397x over previous
#include <cuda_runtime.h>
#include <cuda_bf16.h>
#include <cstdint>
#include <cstddef>

// ---------------------------------------------------------------------------
// MambaBlock: b=2, L=1024, d_model=1024, d_inner=2048, d_state=16, d_conv=4
// bf16x3 mma.sync GEMMs (swizzled smem, 2 CTA/SM, split-K GEMM2)
// + conv/gate + split-K xproj + chunked selective scan
// ---------------------------------------------------------------------------

namespace {
constexpr int kDI   = 2048;
constexpr int kDS   = 16;
constexpr int kL    = 1024;
constexpr int kB    = 2;
constexpr int kDM   = 1024;
constexpr int kRows = kB * kL;        // 2048
constexpr int kNP   = 2 * kDS + 1;    // 33
constexpr int kNCH  = 64;             // scan chunks
constexpr int kTCH  = kL / kNCH;      // 16
constexpr int kPKS  = 4;              // proj K splits

constexpr int MATB   = 128 * 64;              // 8192 (128 rows x 64B)
constexpr int STAGEB = 4 * MATB;              // 32768
constexpr int STAGES = 3;
constexpr int TC_SMEM = STAGES * STAGEB;      // 98304 -> 2 CTAs/SM
}

// Scratch (allocation-free rule: device globals)
__device__ float g_xz[(size_t)kRows * 2 * kDI];
__device__ float g_xh[(size_t)kRows * kDI];
__device__ float g_proj[(size_t)kRows * kNP];
__device__ float g_projp[(size_t)kPKS * kRows * kNP];
__device__ float g_part[(size_t)kRows * kDM];
__device__ float g_aprod [(size_t)kB * kNCH * kDI * kDS];
__device__ float g_hloc  [(size_t)kB * kNCH * kDI * kDS];
__device__ float g_hstart[(size_t)kB * kNCH * kDI * kDS];
__device__ unsigned short g_xhi [(size_t)kRows * kDM];
__device__ unsigned short g_xlo [(size_t)kRows * kDM];
__device__ unsigned short g_wihi[(size_t)2 * kDI * kDM];
__device__ unsigned short g_wilo[(size_t)2 * kDI * kDM];
__device__ unsigned short g_wohi[(size_t)kDM * kDI];
__device__ unsigned short g_wolo[(size_t)kDM * kDI];
__device__ unsigned short g_yhi [(size_t)kRows * kDI];
__device__ unsigned short g_ylo [(size_t)kRows * kDI];

// ---------------------------------------------------------------------------
// PTX helpers
// ---------------------------------------------------------------------------
__device__ __forceinline__ uint32_t smem_u32(const void* p) {
    uint32_t a;
    asm("{ .reg .u64 t; cvta.to.shared.u64 t, %1; cvt.u32.u64 %0, t; }" : "=r"(a) : "l"(p));
    return a;
}
__device__ __forceinline__ void cp16(uint32_t saddr, const void* gaddr) {
    asm volatile("cp.async.cg.shared.global [%0], [%1], 16;" :: "r"(saddr), "l"(gaddr));
}
__device__ __forceinline__ void ldsm_x4(uint32_t a, uint32_t r[4]) {
    asm volatile("ldmatrix.sync.aligned.m8n8.x4.shared.b16 {%0,%1,%2,%3}, [%4];"
                 : "=r"(r[0]), "=r"(r[1]), "=r"(r[2]), "=r"(r[3]) : "r"(a));
}
__device__ __forceinline__ void ldsm_x2(uint32_t a, uint32_t r[2]) {
    asm volatile("ldmatrix.sync.aligned.m8n8.x2.shared.b16 {%0,%1}, [%2];"
                 : "=r"(r[0]), "=r"(r[1]) : "r"(a));
}
__device__ __forceinline__ void mma_bf16(float c[4], const uint32_t a[4], const uint32_t b[2]) {
    asm volatile(
        "mma.sync.aligned.m16n8k16.row.col.f32.bf16.bf16.f32 "
        "{%0,%1,%2,%3}, {%4,%5,%6,%7}, {%8,%9}, {%0,%1,%2,%3};"
        : "+f"(c[0]), "+f"(c[1]), "+f"(c[2]), "+f"(c[3])
        : "r"(a[0]), "r"(a[1]), "r"(a[2]), "r"(a[3]), "r"(b[0]), "r"(b[1]));
}
__device__ __forceinline__ uint32_t swz(uint32_t r, uint32_t c) {
    return r * 64u + ((c ^ ((r >> 1) & 3u)) << 4);
}

// ---------------------------------------------------------------------------
// float -> (bf16 hi, bf16 lo) split: 3 arrays in one launch
// ---------------------------------------------------------------------------
__global__ void __launch_bounds__(256)
cvt3_kernel(const float* __restrict__ a, unsigned short* __restrict__ ahi,
            unsigned short* __restrict__ alo, int na,
            const float* __restrict__ b, unsigned short* __restrict__ bhi,
            unsigned short* __restrict__ blo, int nb,
            const float* __restrict__ c, unsigned short* __restrict__ chi,
            unsigned short* __restrict__ clo, int nc)
{
    int i = blockIdx.x * 256 + threadIdx.x;
    const float* in; unsigned short *hi, *lo;
    if (i < na) { in = a; hi = ahi; lo = alo; }
    else if (i < na + nb) { i -= na; in = b; hi = bhi; lo = blo; }
    else { i -= na + nb; if (i >= nc) return; in = c; hi = chi; lo = clo; }
    const float x = in[i];
    const __nv_bfloat16 h = __float2bfloat16(x);
    hi[i] = __bfloat16_as_ushort(h);
    lo[i] = __bfloat16_as_ushort(__float2bfloat16(x - __bfloat162float(h)));
}

// ---------------------------------------------------------------------------
// bf16x3 NT GEMM: C[m,n] = sum_{k in [z*KL,(z+1)*KL)} A[m,k]*B[n,k] (+bias[n])
// z = blockIdx.z; z==0 writes C, z==1 writes Cpart.
// ---------------------------------------------------------------------------
template <bool BIAS>
__global__ void __launch_bounds__(256, 2)
gemm_bf16x3_kernel(const unsigned short* __restrict__ Ahi,
                   const unsigned short* __restrict__ Alo,
                   const unsigned short* __restrict__ Bhi,
                   const unsigned short* __restrict__ Blo,
                   const float* __restrict__ bias, float* __restrict__ C,
                   float* __restrict__ Cpart, int K, int KL, int N)
{
    extern __shared__ char sm[];
    const uint32_t sbase = smem_u32(sm);
    const int tid  = threadIdx.x;
    const int wid  = tid >> 5;
    const int lane = tid & 31;
    const int m0 = blockIdx.y * 128;
    const int n0 = blockIdx.x * 128;
    const int koff = blockIdx.z * KL;
    const int wm = wid & 1;
    const int wn = wid >> 1;

    const unsigned short* mats[4] = {
        Ahi + (size_t)m0 * K + koff, Alo + (size_t)m0 * K + koff,
        Bhi + (size_t)n0 * K + koff, Blo + (size_t)n0 * K + koff };

    const int NK = KL >> 5;

    const int lm = tid >> 6;
    const int lt = tid & 63;
    const unsigned short* gmat = mats[lm];

    auto issue_stage = [&](int kc) {
        const uint32_t sb = sbase + (uint32_t)(kc % STAGES) * STAGEB + lm * MATB;
        const char* gb = (const char*)(gmat) + (size_t)kc * 64;
#pragma unroll
        for (int j = 0; j < 8; j++) {
            const int id  = lt + j * 64;
            const uint32_t row = id >> 2;
            const uint32_t c16 = id & 3;
            cp16(sb + swz(row, c16), gb + (size_t)row * K * 2 + c16 * 16);
        }
    };

    issue_stage(0);
    asm volatile("cp.async.commit_group;");
    issue_stage(1);
    asm volatile("cp.async.commit_group;");

    float acc[4][4][4];
#pragma unroll
    for (int mt = 0; mt < 4; mt++)
#pragma unroll
        for (int nt = 0; nt < 4; nt++)
#pragma unroll
            for (int r = 0; r < 4; r++) acc[mt][nt][r] = 0.0f;

    const int ag = lane >> 3;
    const uint32_t arow = (ag & 1) * 8 + (lane & 7);
    const uint32_t ac0  = (uint32_t)(ag >> 1);
    const uint32_t brow = lane & 7;
    const uint32_t bc0  = (uint32_t)((lane >> 3) & 1);

    for (int kc = 0; kc < NK; kc++) {
        asm volatile("cp.async.wait_group 1;");
        __syncthreads();
        if (kc + 2 < NK) issue_stage(kc + 2);
        asm volatile("cp.async.commit_group;");

        const uint32_t stg = sbase + (uint32_t)(kc % STAGES) * STAGEB;
        const uint32_t bAhi = stg + 0 * MATB;
        const uint32_t bAlo = stg + 1 * MATB;
        const uint32_t bBhi = stg + 2 * MATB;
        const uint32_t bBlo = stg + 3 * MATB;

#pragma unroll
        for (int kh = 0; kh < 2; kh++) {
            const uint32_t ca = ac0 + kh * 2;
            const uint32_t cb = bc0 + kh * 2;
            uint32_t fBh[4][2], fBl[4][2];
#pragma unroll
            for (int nt = 0; nt < 4; nt++) {
                const uint32_t rB = wn * 32 + nt * 8 + brow;
                const uint32_t o = swz(rB, cb);
                ldsm_x2(bBhi + o, fBh[nt]);
                ldsm_x2(bBlo + o, fBl[nt]);
            }
#pragma unroll
            for (int mt = 0; mt < 4; mt++) {
                const uint32_t rA = wm * 64 + mt * 16 + arow;
                const uint32_t o = swz(rA, ca);
                uint32_t fAh[4], fAl[4];
                ldsm_x4(bAhi + o, fAh);
                ldsm_x4(bAlo + o, fAl);
#pragma unroll
                for (int nt = 0; nt < 4; nt++) {
                    mma_bf16(acc[mt][nt], fAh, fBh[nt]);
                    mma_bf16(acc[mt][nt], fAh, fBl[nt]);
                    mma_bf16(acc[mt][nt], fAl, fBh[nt]);
                }
            }
        }
    }

    float* Cout = blockIdx.z ? Cpart : C;
    const int gid = lane >> 2;
    const int tig = lane & 3;
#pragma unroll
    for (int mt = 0; mt < 4; mt++) {
        const int r0 = m0 + wm * 64 + mt * 16 + gid;
#pragma unroll
        for (int nt = 0; nt < 4; nt++) {
            const int c = n0 + wn * 32 + nt * 8 + 2 * tig;
            float b0 = 0.0f, b1 = 0.0f;
            if (BIAS) { b0 = bias[c]; b1 = bias[c + 1]; }
            float2 v0 = make_float2(acc[mt][nt][0] + b0, acc[mt][nt][1] + b1);
            float2 v1 = make_float2(acc[mt][nt][2] + b0, acc[mt][nt][3] + b1);
            *(float2*)(&Cout[(size_t)r0 * N + c])       = v0;
            *(float2*)(&Cout[(size_t)(r0 + 8) * N + c]) = v1;
        }
    }
}

// out += part (float4)
__global__ void __launch_bounds__(256)
add_kernel(float* __restrict__ out, const float* __restrict__ part, int n4)
{
    const int i = blockIdx.x * 256 + threadIdx.x;
    if (i < n4) {
        float4 o = ((const float4*)out)[i];
        const float4 p = ((const float4*)part)[i];
        o.x += p.x; o.y += p.y; o.z += p.z; o.w += p.w;
        ((float4*)out)[i] = o;
    }
}

// ---------------------------------------------------------------------------
// Depthwise causal conv (D_CONV=4) + bias + SiLU(z) gate.
// ---------------------------------------------------------------------------
__global__ void __launch_bounds__(256)
conv_gate_kernel(const float* __restrict__ conv_w,
                 const float* __restrict__ conv_b)
{
    const int idx = blockIdx.x * 256 + threadIdx.x;
    const int i = idx & (kDI - 1);
    const int t = (idx >> 11) & (kL - 1);
    const int b = idx >> 21;

    const float* base = g_xz + (size_t)b * kL * (2 * kDI) + i;
    float accv = conv_b[i];
#pragma unroll
    for (int k = 0; k < 4; k++) {
        const int tt = t + k - 3;
        if (tt >= 0) accv += conv_w[i * 4 + k] * base[(size_t)tt * (2 * kDI)];
    }
    const float z = g_xz[((size_t)(b * kL + t)) * (2 * kDI) + kDI + i];
    const float sig = 1.0f / (1.0f + __expf(-z));
    g_xh[idx] = accv * (z * sig);
}

// ---------------------------------------------------------------------------
// proj partials: block = 8 rows (one per warp), grid.y = K split of 512.
// Lanes cover each 128-k chunk as float4; w chunk staged in smem.
// ---------------------------------------------------------------------------
__global__ void __launch_bounds__(256)
proj_kernel(const float* __restrict__ w)
{
    constexpr int KQ = kDI / kPKS;   // 512
    constexpr int KC = 128;
    __shared__ float4 ws[kNP][KC / 4];   // 33 x 32 float4 = 16.9KB

    const int warp = threadIdx.x >> 5;
    const int lane = threadIdx.x & 31;
    const int row = blockIdx.x * 8 + warp;
    const int kq0 = blockIdx.y * KQ;

    float acc[kNP];
#pragma unroll
    for (int n = 0; n < kNP; n++) acc[n] = 0.0f;

#pragma unroll
    for (int c = 0; c < KQ / KC; c++) {
        __syncthreads();
        for (int idx = threadIdx.x; idx < kNP * (KC / 4); idx += 256) {
            const int n = idx >> 5;
            const int q = idx & 31;
            ws[n][q] = *(const float4*)&w[(size_t)n * kDI + kq0 + c * KC + q * 4];
        }
        __syncthreads();
        const float4 xv = *(const float4*)&g_xh[(size_t)row * kDI + kq0 + c * KC + lane * 4];
#pragma unroll
        for (int n = 0; n < kNP; n++) {
            const float4 wv = ws[n][lane];
            acc[n] += xv.x * wv.x + xv.y * wv.y + xv.z * wv.z + xv.w * wv.w;
        }
    }

#pragma unroll
    for (int n = 0; n < kNP; n++) {
#pragma unroll
        for (int off = 16; off > 0; off >>= 1)
            acc[n] += __shfl_xor_sync(0xFFFFFFFFu, acc[n], off);
    }
    if (lane == 0) {
        float* o = g_projp + ((size_t)blockIdx.y * kRows + row) * kNP;
#pragma unroll
        for (int n = 0; n < kNP; n++) o[n] = acc[n];
    }
}

// combine kPKS partials -> g_proj (deterministic, no atomics)
__global__ void __launch_bounds__(256)
proj_combine_kernel()
{
    const int i = blockIdx.x * 256 + threadIdx.x;
    if (i >= kRows * kNP) return;
    float s = 0.0f;
#pragma unroll
    for (int z = 0; z < kPKS; z++)
        s += g_projp[(size_t)z * kRows * kNP + i];
    g_proj[i] = s;
}

// ---------------------------------------------------------------------------
// Chunked selective scan. delta = exp(softplus(.)) = 1 + exp(.) identity.
// ---------------------------------------------------------------------------
__global__ void __launch_bounds__(256)
scan_pass1_kernel(const float* __restrict__ dt_w,
                  const float* __restrict__ dt_b,
                  const float* __restrict__ A_log)
{
    const int gi = blockIdx.x;
    const int b = gi / (kNCH * (kDI / 256));
    const int c = (gi / (kDI / 256)) % kNCH;
    const int i = (gi % (kDI / 256)) * 256 + threadIdx.x;

    constexpr float kLog2e = 1.4426950408889634f;
    float Arow[kDS], h[kDS], P[kDS];
#pragma unroll
    for (int s = 0; s < kDS; s++) {
        Arow[s] = -__expf(A_log[i * kDS + s]) * kLog2e;
        h[s] = 0.0f;
        P[s] = 1.0f;
    }
    const float dtw = dt_w[i];
    const float dtb = dt_b[i];

    __shared__ float sp[kTCH * kNP];
    {
        const size_t base = (size_t)(b * kL + c * kTCH) * kNP;
        for (int idx = threadIdx.x; idx < kTCH * kNP; idx += 256)
            sp[idx] = g_proj[base + idx];
    }
    __syncthreads();

    for (int tt = 0; tt < kTCH; tt++) {
        const int t = c * kTCH + tt;
        const float* row = sp + tt * kNP;
        const float xt = g_xh[((size_t)(b * kL + t)) * kDI + i];
        const float delta = 1.0f + __expf(row[0] * dtw + dtb);
        const float dx = delta * xt;
#pragma unroll
        for (int s = 0; s < kDS; s++) {
            const float a = exp2f(Arow[s] * delta);
            h[s] = a * h[s] + row[1 + s] * dx;
            P[s] *= a;
        }
    }

    const size_t o = (((size_t)(b * kNCH + c)) * kDI + i) * kDS;
#pragma unroll
    for (int v = 0; v < kDS / 4; v++) {
        *(float4*)(g_aprod + o + v * 4) = make_float4(P[v*4], P[v*4+1], P[v*4+2], P[v*4+3]);
        *(float4*)(g_hloc  + o + v * 4) = make_float4(h[v*4], h[v*4+1], h[v*4+2], h[v*4+3]);
    }
}

__global__ void __launch_bounds__(256)
scan_combine_kernel()
{
    const int idx = blockIdx.x * 256 + threadIdx.x;
    const int b = idx >> 15;
    const int rem = idx & ((kDI * kDS) - 1);
    float h = 0.0f;
#pragma unroll 4
    for (int c = 0; c < kNCH; c++) {
        const size_t o = ((size_t)(b * kNCH + c)) * (kDI * kDS) + rem;
        g_hstart[o] = h;
        h = g_aprod[o] * h + g_hloc[o];
    }
}

__global__ void __launch_bounds__(256)
scan_pass3_kernel(const float* __restrict__ dt_w,
                  const float* __restrict__ dt_b,
                  const float* __restrict__ A_log,
                  const float* __restrict__ Dv)
{
    const int gi = blockIdx.x;
    const int b = gi / (kNCH * (kDI / 256));
    const int c = (gi / (kDI / 256)) % kNCH;
    const int i = (gi % (kDI / 256)) * 256 + threadIdx.x;

    constexpr float kLog2e = 1.4426950408889634f;
    float Arow[kDS], h[kDS];
    {
        const size_t o = (((size_t)(b * kNCH + c)) * kDI + i) * kDS;
#pragma unroll
        for (int v = 0; v < kDS / 4; v++) {
            float4 hv = *(const float4*)(g_hstart + o + v * 4);
            h[v*4] = hv.x; h[v*4+1] = hv.y; h[v*4+2] = hv.z; h[v*4+3] = hv.w;
        }
    }
#pragma unroll
    for (int s = 0; s < kDS; s++)
        Arow[s] = -__expf(A_log[i * kDS + s]) * kLog2e;

    const float dtw = dt_w[i];
    const float dtb = dt_b[i];
    const float Di  = Dv[i];

    __shared__ float sp[kTCH * kNP];
    {
        const size_t base = (size_t)(b * kL + c * kTCH) * kNP;
        for (int idx = threadIdx.x; idx < kTCH * kNP; idx += 256)
            sp[idx] = g_proj[base + idx];
    }
    __syncthreads();

    for (int tt = 0; tt < kTCH; tt++) {
        const int t = c * kTCH + tt;
        const float* row = sp + tt * kNP;
        const size_t oy = ((size_t)(b * kL + t)) * kDI + i;
        const float xt = g_xh[oy];
        const float delta = 1.0f + __expf(row[0] * dtw + dtb);
        const float dx = delta * xt;
        float yv = 0.0f;
#pragma unroll
        for (int s = 0; s < kDS; s++) {
            const float a = exp2f(Arow[s] * delta);
            h[s] = a * h[s] + row[1 + s] * dx;
            yv += h[s] * row[1 + kDS + s];
        }
        const float yf = yv + Di * xt;
        const __nv_bfloat16 hy = __float2bfloat16(yf);
        g_yhi[oy] = __bfloat16_as_ushort(hy);
        g_ylo[oy] = __bfloat16_as_ushort(__float2bfloat16(yf - __bfloat162float(hy)));
    }
}

// ---------------------------------------------------------------------------
// Launch
// ---------------------------------------------------------------------------
extern "C" void kernel_launch(void* const* d_in, const int* in_sizes, int n_in,
                              void* d_out, int out_size)
{
    const float* x       = (const float*)d_in[0];
    const float* in_w    = (const float*)d_in[1];
    const float* in_b    = (const float*)d_in[2];
    const float* conv_w  = (const float*)d_in[3];
    const float* conv_b  = (const float*)d_in[4];
    const float* xproj_w = (const float*)d_in[5];
    const float* dt_w    = (const float*)d_in[6];
    const float* dt_b    = (const float*)d_in[7];
    const float* A_log   = (const float*)d_in[8];
    const float* Dv      = (const float*)d_in[9];
    const float* out_w   = (const float*)d_in[10];
    float* out = (float*)d_out;

    float *xz_p, *part_p;
    unsigned short *xhi, *xlo, *wihi, *wilo, *wohi, *wolo, *yhi, *ylo;
    cudaGetSymbolAddress((void**)&xz_p,   g_xz);
    cudaGetSymbolAddress((void**)&part_p, g_part);
    cudaGetSymbolAddress((void**)&xhi,  g_xhi);
    cudaGetSymbolAddress((void**)&xlo,  g_xlo);
    cudaGetSymbolAddress((void**)&wihi, g_wihi);
    cudaGetSymbolAddress((void**)&wilo, g_wilo);
    cudaGetSymbolAddress((void**)&wohi, g_wohi);
    cudaGetSymbolAddress((void**)&wolo, g_wolo);
    cudaGetSymbolAddress((void**)&yhi,  g_yhi);
    cudaGetSymbolAddress((void**)&ylo,  g_ylo);

    cudaFuncSetAttribute(gemm_bf16x3_kernel<true>,
                         cudaFuncAttributeMaxDynamicSharedMemorySize, TC_SMEM);
    cudaFuncSetAttribute(gemm_bf16x3_kernel<false>,
                         cudaFuncAttributeMaxDynamicSharedMemorySize, TC_SMEM);

    // hi/lo splits (one launch)
    {
        const int n1 = kRows * kDM;        // x
        const int n2 = 2 * kDI * kDM;      // in_w
        const int n3 = kDM * kDI;          // out_w
        const int tot = n1 + n2 + n3;
        cvt3_kernel<<<(tot + 255) / 256, 256>>>(x, xhi, xlo, n1,
                                                in_w, wihi, wilo, n2,
                                                out_w, wohi, wolo, n3);
    }

    // GEMM1: xz = x @ in_w^T + in_b   (M=2048, N=4096, K=1024)
    {
        dim3 grid((2 * kDI) / 128, kRows / 128, 1);
        gemm_bf16x3_kernel<true><<<grid, 256, TC_SMEM>>>(
            xhi, xlo, wihi, wilo, in_b, xz_p, nullptr, kDM, kDM, 2 * kDI);
    }
    // conv + SiLU gate
    conv_gate_kernel<<<(kRows * kDI) / 256, 256>>>(conv_w, conv_b);
    // xproj: split-K partials + combine
    {
        dim3 grid(kRows / 8, kPKS);
        proj_kernel<<<grid, 256>>>(xproj_w);
        proj_combine_kernel<<<(kRows * kNP + 255) / 256, 256>>>();
    }
    // chunked selective scan (pass3 emits y as bf16 hi/lo)
    {
        const int grid_scan = kB * kNCH * (kDI / 256);   // 1024
        scan_pass1_kernel<<<grid_scan, 256>>>(dt_w, dt_b, A_log);
        scan_combine_kernel<<<(kB * kDI * kDS) / 256, 256>>>();
        scan_pass3_kernel<<<grid_scan, 256>>>(dt_w, dt_b, A_log, Dv);
    }
    // GEMM2: out = y @ out_w^T  (M=2048, N=1024, K=2048), split-K=2
    {
        dim3 grid(kDM / 128, kRows / 128, 2);
        gemm_bf16x3_kernel<false><<<grid, 256, TC_SMEM>>>(
            yhi, ylo, wohi, wolo, nullptr, out, part_p, kDI, kDI / 2, kDM);
        add_kernel<<<(kRows * kDM / 4 + 255) / 256, 256>>>(out, part_p, kRows * kDM / 4);
    }
}

// round 13
// speedup vs baseline: 3.5002x; 1.0587x over previous
#include <cuda_runtime.h>
#include <cuda_bf16.h>
#include <cstdint>
#include <cstddef>

// ---------------------------------------------------------------------------
// MambaBlock: b=2, L=1024, d_model=1024, d_inner=2048, d_state=16, d_conv=4
// bf16x3 mma.sync GEMMs everywhere (GEMM1, xproj, GEMM2) + conv/gate + scan
// ---------------------------------------------------------------------------

namespace {
constexpr int kDI   = 2048;
constexpr int kDS   = 16;
constexpr int kL    = 1024;
constexpr int kB    = 2;
constexpr int kDM   = 1024;
constexpr int kRows = kB * kL;        // 2048
constexpr int kNP   = 2 * kDS + 1;    // 33
constexpr int kNPP  = 128;            // padded proj N
constexpr int kNCH  = 64;             // scan chunks
constexpr int kTCH  = kL / kNCH;      // 16
constexpr int kPKS  = 8;              // proj K splits

constexpr int MATB   = 128 * 64;              // 8192 (128 rows x 64B)
constexpr int STAGEB = 4 * MATB;              // 32768
constexpr int STAGES = 3;
constexpr int TC_SMEM = STAGES * STAGEB;      // 98304 -> 2 CTAs/SM
}

// Scratch (allocation-free rule: device globals)
__device__ float g_xz[(size_t)kRows * 2 * kDI];
__device__ float g_xh[(size_t)kRows * kDI];
__device__ float g_proj[(size_t)kRows * kNP];
__device__ float g_projp[(size_t)kPKS * kRows * kNPP];
__device__ float g_part[(size_t)kRows * kDM];
__device__ float g_aprod [(size_t)kB * kNCH * kDI * kDS];
__device__ float g_hloc  [(size_t)kB * kNCH * kDI * kDS];
__device__ float g_hstart[(size_t)kB * kNCH * kDI * kDS];
__device__ unsigned short g_xhi [(size_t)kRows * kDM];
__device__ unsigned short g_xlo [(size_t)kRows * kDM];
__device__ unsigned short g_wihi[(size_t)2 * kDI * kDM];
__device__ unsigned short g_wilo[(size_t)2 * kDI * kDM];
__device__ unsigned short g_wohi[(size_t)kDM * kDI];
__device__ unsigned short g_wolo[(size_t)kDM * kDI];
__device__ unsigned short g_wphi[(size_t)kNPP * kDI];
__device__ unsigned short g_wplo[(size_t)kNPP * kDI];
__device__ unsigned short g_xhhi[(size_t)kRows * kDI];
__device__ unsigned short g_xhlo[(size_t)kRows * kDI];
__device__ unsigned short g_yhi [(size_t)kRows * kDI];
__device__ unsigned short g_ylo [(size_t)kRows * kDI];

// ---------------------------------------------------------------------------
// PTX helpers
// ---------------------------------------------------------------------------
__device__ __forceinline__ uint32_t smem_u32(const void* p) {
    uint32_t a;
    asm("{ .reg .u64 t; cvta.to.shared.u64 t, %1; cvt.u32.u64 %0, t; }" : "=r"(a) : "l"(p));
    return a;
}
__device__ __forceinline__ void cp16(uint32_t saddr, const void* gaddr) {
    asm volatile("cp.async.cg.shared.global [%0], [%1], 16;" :: "r"(saddr), "l"(gaddr));
}
__device__ __forceinline__ void ldsm_x4(uint32_t a, uint32_t r[4]) {
    asm volatile("ldmatrix.sync.aligned.m8n8.x4.shared.b16 {%0,%1,%2,%3}, [%4];"
                 : "=r"(r[0]), "=r"(r[1]), "=r"(r[2]), "=r"(r[3]) : "r"(a));
}
__device__ __forceinline__ void mma_bf16(float c[4], const uint32_t a[4], const uint32_t b[2]) {
    asm volatile(
        "mma.sync.aligned.m16n8k16.row.col.f32.bf16.bf16.f32 "
        "{%0,%1,%2,%3}, {%4,%5,%6,%7}, {%8,%9}, {%0,%1,%2,%3};"
        : "+f"(c[0]), "+f"(c[1]), "+f"(c[2]), "+f"(c[3])
        : "r"(a[0]), "r"(a[1]), "r"(a[2]), "r"(a[3]), "r"(b[0]), "r"(b[1]));
}
__device__ __forceinline__ uint32_t swz(uint32_t r, uint32_t c) {
    return r * 64u + ((c ^ ((r >> 1) & 3u)) << 4);
}
__device__ __forceinline__ void split_bf16(float x, unsigned short& hi, unsigned short& lo) {
    const __nv_bfloat16 h = __float2bfloat16(x);
    hi = __bfloat16_as_ushort(h);
    lo = __bfloat16_as_ushort(__float2bfloat16(x - __bfloat162float(h)));
}

// ---------------------------------------------------------------------------
// float -> (bf16 hi, bf16 lo) split: 3 arrays in one launch
// ---------------------------------------------------------------------------
__global__ void __launch_bounds__(256)
cvt3_kernel(const float* __restrict__ a, unsigned short* __restrict__ ahi,
            unsigned short* __restrict__ alo, int na,
            const float* __restrict__ b, unsigned short* __restrict__ bhi,
            unsigned short* __restrict__ blo, int nb,
            const float* __restrict__ c, unsigned short* __restrict__ chi,
            unsigned short* __restrict__ clo, int nc)
{
    int i = blockIdx.x * 256 + threadIdx.x;
    const float* in; unsigned short *hi, *lo;
    if (i < na) { in = a; hi = ahi; lo = alo; }
    else if (i < na + nb) { i -= na; in = b; hi = bhi; lo = blo; }
    else { i -= na + nb; if (i >= nc) return; in = c; hi = chi; lo = clo; }
    split_bf16(in[i], hi[i], lo[i]);
}

// padded xproj_w (33 -> 128 rows, zeros) hi/lo split
__global__ void __launch_bounds__(256)
cvt_wpad_kernel(const float* __restrict__ w)
{
    const int idx = blockIdx.x * 256 + threadIdx.x;   // over kNPP*kDI
    if (idx >= kNPP * kDI) return;
    const int n = idx >> 11;
    const float v = (n < kNP) ? w[idx] : 0.0f;
    split_bf16(v, g_wphi[idx], g_wplo[idx]);
}

// ---------------------------------------------------------------------------
// bf16x3 NT GEMM: C[m,n] = sum_{k in [z*KL,(z+1)*KL)} A[m,k]*B[n,k] (+bias[n])
// z=0 writes C; z>=1 writes Cpart + (z-1)*zstride.
// ---------------------------------------------------------------------------
template <bool BIAS>
__global__ void __launch_bounds__(256, 2)
gemm_bf16x3_kernel(const unsigned short* __restrict__ Ahi,
                   const unsigned short* __restrict__ Alo,
                   const unsigned short* __restrict__ Bhi,
                   const unsigned short* __restrict__ Blo,
                   const float* __restrict__ bias, float* __restrict__ C,
                   float* __restrict__ Cpart, size_t zstride, int K, int KL, int N)
{
    extern __shared__ char sm[];
    const uint32_t sbase = smem_u32(sm);
    const int tid  = threadIdx.x;
    const int wid  = tid >> 5;
    const int lane = tid & 31;
    const int m0 = blockIdx.y * 128;
    const int n0 = blockIdx.x * 128;
    const int koff = blockIdx.z * KL;
    const int wm = wid & 1;
    const int wn = wid >> 1;

    const unsigned short* mats[4] = {
        Ahi + (size_t)m0 * K + koff, Alo + (size_t)m0 * K + koff,
        Bhi + (size_t)n0 * K + koff, Blo + (size_t)n0 * K + koff };

    const int NK = KL >> 5;

    const int lm = tid >> 6;
    const int lt = tid & 63;
    const unsigned short* gmat = mats[lm];

    auto issue_stage = [&](int kc) {
        const uint32_t sb = sbase + (uint32_t)(kc % STAGES) * STAGEB + lm * MATB;
        const char* gb = (const char*)(gmat) + (size_t)kc * 64;
#pragma unroll
        for (int j = 0; j < 8; j++) {
            const int id  = lt + j * 64;
            const uint32_t row = id >> 2;
            const uint32_t c16 = id & 3;
            cp16(sb + swz(row, c16), gb + (size_t)row * K * 2 + c16 * 16);
        }
    };

    issue_stage(0);
    asm volatile("cp.async.commit_group;");
    issue_stage(1);
    asm volatile("cp.async.commit_group;");

    float acc[4][4][4];
#pragma unroll
    for (int mt = 0; mt < 4; mt++)
#pragma unroll
        for (int nt = 0; nt < 4; nt++)
#pragma unroll
            for (int r = 0; r < 4; r++) acc[mt][nt][r] = 0.0f;

    const int ag = lane >> 3;
    const uint32_t arow = (ag & 1) * 8 + (lane & 7);
    const uint32_t ac0  = (uint32_t)(ag >> 1);
    // B x4 addressing: lanes 0-7 -> ntp*16+0..7 chunk0, 8-15 -> chunk1,
    // 16-23 -> ntp*16+8..15 chunk0, 24-31 -> chunk1
    const uint32_t brow4 = ((lane >> 4) & 1) * 8 + (lane & 7);
    const uint32_t bc0   = (uint32_t)((lane >> 3) & 1);

    for (int kc = 0; kc < NK; kc++) {
        asm volatile("cp.async.wait_group 1;");
        __syncthreads();
        if (kc + 2 < NK) issue_stage(kc + 2);
        asm volatile("cp.async.commit_group;");

        const uint32_t stg = sbase + (uint32_t)(kc % STAGES) * STAGEB;
        const uint32_t bAhi = stg + 0 * MATB;
        const uint32_t bAlo = stg + 1 * MATB;
        const uint32_t bBhi = stg + 2 * MATB;
        const uint32_t bBlo = stg + 3 * MATB;

#pragma unroll
        for (int kh = 0; kh < 2; kh++) {
            const uint32_t ca = ac0 + kh * 2;
            const uint32_t cb = bc0 + kh * 2;
            uint32_t fBh[4][2], fBl[4][2];
#pragma unroll
            for (int ntp = 0; ntp < 2; ntp++) {
                const uint32_t rB = wn * 32 + ntp * 16 + brow4;
                const uint32_t o = swz(rB, cb);
                ldsm_x4(bBhi + o, fBh[ntp * 2]);   // fills [ntp*2][0..1],[ntp*2+1][0..1]
                ldsm_x4(bBlo + o, fBl[ntp * 2]);
            }
#pragma unroll
            for (int mt = 0; mt < 4; mt++) {
                const uint32_t rA = wm * 64 + mt * 16 + arow;
                const uint32_t o = swz(rA, ca);
                uint32_t fAh[4], fAl[4];
                ldsm_x4(bAhi + o, fAh);
                ldsm_x4(bAlo + o, fAl);
#pragma unroll
                for (int nt = 0; nt < 4; nt++) {
                    mma_bf16(acc[mt][nt], fAh, fBh[nt]);
                    mma_bf16(acc[mt][nt], fAh, fBl[nt]);
                    mma_bf16(acc[mt][nt], fAl, fBh[nt]);
                }
            }
        }
    }

    float* Cout = (blockIdx.z == 0) ? C : (Cpart + (size_t)(blockIdx.z - 1) * zstride);
    const int gid = lane >> 2;
    const int tig = lane & 3;
#pragma unroll
    for (int mt = 0; mt < 4; mt++) {
        const int r0 = m0 + wm * 64 + mt * 16 + gid;
#pragma unroll
        for (int nt = 0; nt < 4; nt++) {
            const int c = n0 + wn * 32 + nt * 8 + 2 * tig;
            float b0 = 0.0f, b1 = 0.0f;
            if (BIAS) { b0 = bias[c]; b1 = bias[c + 1]; }
            float2 v0 = make_float2(acc[mt][nt][0] + b0, acc[mt][nt][1] + b1);
            float2 v1 = make_float2(acc[mt][nt][2] + b0, acc[mt][nt][3] + b1);
            *(float2*)(&Cout[(size_t)r0 * N + c])       = v0;
            *(float2*)(&Cout[(size_t)(r0 + 8) * N + c]) = v1;
        }
    }
}

// out += part (float4)
__global__ void __launch_bounds__(256)
add_kernel(float* __restrict__ out, const float* __restrict__ part, int n4)
{
    const int i = blockIdx.x * 256 + threadIdx.x;
    if (i < n4) {
        float4 o = ((const float4*)out)[i];
        const float4 p = ((const float4*)part)[i];
        o.x += p.x; o.y += p.y; o.z += p.z; o.w += p.w;
        ((float4*)out)[i] = o;
    }
}

// combine kPKS proj partials (N=128 padded) -> g_proj (N=33)
__global__ void __launch_bounds__(256)
proj_combine_kernel()
{
    const int i = blockIdx.x * 256 + threadIdx.x;
    if (i >= kRows * kNP) return;
    const int row = i / kNP;
    const int n = i - row * kNP;
    float s = 0.0f;
#pragma unroll
    for (int z = 0; z < kPKS; z++)
        s += g_projp[((size_t)z * kRows + row) * kNPP + n];
    g_proj[i] = s;
}

// ---------------------------------------------------------------------------
// Depthwise causal conv (D_CONV=4) + bias + SiLU(z) gate.
// Also emits xh as bf16 hi/lo for the proj GEMM.
// ---------------------------------------------------------------------------
__global__ void __launch_bounds__(256)
conv_gate_kernel(const float* __restrict__ conv_w,
                 const float* __restrict__ conv_b)
{
    const int idx = blockIdx.x * 256 + threadIdx.x;
    const int i = idx & (kDI - 1);
    const int t = (idx >> 11) & (kL - 1);
    const int b = idx >> 21;

    const float* base = g_xz + (size_t)b * kL * (2 * kDI) + i;
    float accv = conv_b[i];
#pragma unroll
    for (int k = 0; k < 4; k++) {
        const int tt = t + k - 3;
        if (tt >= 0) accv += conv_w[i * 4 + k] * base[(size_t)tt * (2 * kDI)];
    }
    const float z = g_xz[((size_t)(b * kL + t)) * (2 * kDI) + kDI + i];
    const float sig = 1.0f / (1.0f + __expf(-z));
    const float xh = accv * (z * sig);
    g_xh[idx] = xh;
    split_bf16(xh, g_xhhi[idx], g_xhlo[idx]);
}

// ---------------------------------------------------------------------------
// Chunked selective scan. delta = exp(softplus(.)) = 1 + exp(.) identity.
// ---------------------------------------------------------------------------
__global__ void __launch_bounds__(256)
scan_pass1_kernel(const float* __restrict__ dt_w,
                  const float* __restrict__ dt_b,
                  const float* __restrict__ A_log)
{
    const int gi = blockIdx.x;
    const int b = gi / (kNCH * (kDI / 256));
    const int c = (gi / (kDI / 256)) % kNCH;
    const int i = (gi % (kDI / 256)) * 256 + threadIdx.x;

    constexpr float kLog2e = 1.4426950408889634f;
    float Arow[kDS], h[kDS], P[kDS];
#pragma unroll
    for (int s = 0; s < kDS; s++) {
        Arow[s] = -__expf(A_log[i * kDS + s]) * kLog2e;
        h[s] = 0.0f;
        P[s] = 1.0f;
    }
    const float dtw = dt_w[i];
    const float dtb = dt_b[i];

    __shared__ float sp[kTCH * kNP];
    {
        const size_t base = (size_t)(b * kL + c * kTCH) * kNP;
        for (int idx = threadIdx.x; idx < kTCH * kNP; idx += 256)
            sp[idx] = g_proj[base + idx];
    }
    __syncthreads();

    for (int tt = 0; tt < kTCH; tt++) {
        const int t = c * kTCH + tt;
        const float* row = sp + tt * kNP;
        const float xt = g_xh[((size_t)(b * kL + t)) * kDI + i];
        const float delta = 1.0f + __expf(row[0] * dtw + dtb);
        const float dx = delta * xt;
#pragma unroll
        for (int s = 0; s < kDS; s++) {
            const float a = exp2f(Arow[s] * delta);
            h[s] = a * h[s] + row[1 + s] * dx;
            P[s] *= a;
        }
    }

    const size_t o = (((size_t)(b * kNCH + c)) * kDI + i) * kDS;
#pragma unroll
    for (int v = 0; v < kDS / 4; v++) {
        *(float4*)(g_aprod + o + v * 4) = make_float4(P[v*4], P[v*4+1], P[v*4+2], P[v*4+3]);
        *(float4*)(g_hloc  + o + v * 4) = make_float4(h[v*4], h[v*4+1], h[v*4+2], h[v*4+3]);
    }
}

__global__ void __launch_bounds__(256)
scan_combine_kernel()
{
    const int idx = blockIdx.x * 256 + threadIdx.x;
    const int b = idx >> 15;
    const int rem = idx & ((kDI * kDS) - 1);
    float h = 0.0f;
#pragma unroll 4
    for (int c = 0; c < kNCH; c++) {
        const size_t o = ((size_t)(b * kNCH + c)) * (kDI * kDS) + rem;
        g_hstart[o] = h;
        h = g_aprod[o] * h + g_hloc[o];
    }
}

__global__ void __launch_bounds__(256)
scan_pass3_kernel(const float* __restrict__ dt_w,
                  const float* __restrict__ dt_b,
                  const float* __restrict__ A_log,
                  const float* __restrict__ Dv)
{
    const int gi = blockIdx.x;
    const int b = gi / (kNCH * (kDI / 256));
    const int c = (gi / (kDI / 256)) % kNCH;
    const int i = (gi % (kDI / 256)) * 256 + threadIdx.x;

    constexpr float kLog2e = 1.4426950408889634f;
    float Arow[kDS], h[kDS];
    {
        const size_t o = (((size_t)(b * kNCH + c)) * kDI + i) * kDS;
#pragma unroll
        for (int v = 0; v < kDS / 4; v++) {
            float4 hv = *(const float4*)(g_hstart + o + v * 4);
            h[v*4] = hv.x; h[v*4+1] = hv.y; h[v*4+2] = hv.z; h[v*4+3] = hv.w;
        }
    }
#pragma unroll
    for (int s = 0; s < kDS; s++)
        Arow[s] = -__expf(A_log[i * kDS + s]) * kLog2e;

    const float dtw = dt_w[i];
    const float dtb = dt_b[i];
    const float Di  = Dv[i];

    __shared__ float sp[kTCH * kNP];
    {
        const size_t base = (size_t)(b * kL + c * kTCH) * kNP;
        for (int idx = threadIdx.x; idx < kTCH * kNP; idx += 256)
            sp[idx] = g_proj[base + idx];
    }
    __syncthreads();

    for (int tt = 0; tt < kTCH; tt++) {
        const int t = c * kTCH + tt;
        const float* row = sp + tt * kNP;
        const size_t oy = ((size_t)(b * kL + t)) * kDI + i;
        const float xt = g_xh[oy];
        const float delta = 1.0f + __expf(row[0] * dtw + dtb);
        const float dx = delta * xt;
        float yv = 0.0f;
#pragma unroll
        for (int s = 0; s < kDS; s++) {
            const float a = exp2f(Arow[s] * delta);
            h[s] = a * h[s] + row[1 + s] * dx;
            yv += h[s] * row[1 + kDS + s];
        }
        const float yf = yv + Di * xt;
        split_bf16(yf, g_yhi[oy], g_ylo[oy]);
    }
}

// ---------------------------------------------------------------------------
// Launch
// ---------------------------------------------------------------------------
extern "C" void kernel_launch(void* const* d_in, const int* in_sizes, int n_in,
                              void* d_out, int out_size)
{
    const float* x       = (const float*)d_in[0];
    const float* in_w    = (const float*)d_in[1];
    const float* in_b    = (const float*)d_in[2];
    const float* conv_w  = (const float*)d_in[3];
    const float* conv_b  = (const float*)d_in[4];
    const float* xproj_w = (const float*)d_in[5];
    const float* dt_w    = (const float*)d_in[6];
    const float* dt_b    = (const float*)d_in[7];
    const float* A_log   = (const float*)d_in[8];
    const float* Dv      = (const float*)d_in[9];
    const float* out_w   = (const float*)d_in[10];
    float* out = (float*)d_out;

    float *xz_p, *part_p, *projp_p;
    unsigned short *xhi, *xlo, *wihi, *wilo, *wohi, *wolo, *yhi, *ylo;
    unsigned short *wphi, *wplo, *xhhi, *xhlo;
    cudaGetSymbolAddress((void**)&xz_p,    g_xz);
    cudaGetSymbolAddress((void**)&part_p,  g_part);
    cudaGetSymbolAddress((void**)&projp_p, g_projp);
    cudaGetSymbolAddress((void**)&xhi,  g_xhi);
    cudaGetSymbolAddress((void**)&xlo,  g_xlo);
    cudaGetSymbolAddress((void**)&wihi, g_wihi);
    cudaGetSymbolAddress((void**)&wilo, g_wilo);
    cudaGetSymbolAddress((void**)&wohi, g_wohi);
    cudaGetSymbolAddress((void**)&wolo, g_wolo);
    cudaGetSymbolAddress((void**)&wphi, g_wphi);
    cudaGetSymbolAddress((void**)&wplo, g_wplo);
    cudaGetSymbolAddress((void**)&xhhi, g_xhhi);
    cudaGetSymbolAddress((void**)&xhlo, g_xhlo);
    cudaGetSymbolAddress((void**)&yhi,  g_yhi);
    cudaGetSymbolAddress((void**)&ylo,  g_ylo);

    cudaFuncSetAttribute(gemm_bf16x3_kernel<true>,
                         cudaFuncAttributeMaxDynamicSharedMemorySize, TC_SMEM);
    cudaFuncSetAttribute(gemm_bf16x3_kernel<false>,
                         cudaFuncAttributeMaxDynamicSharedMemorySize, TC_SMEM);

    // hi/lo splits (x, in_w, out_w) + padded xproj_w
    {
        const int n1 = kRows * kDM;
        const int n2 = 2 * kDI * kDM;
        const int n3 = kDM * kDI;
        const int tot = n1 + n2 + n3;
        cvt3_kernel<<<(tot + 255) / 256, 256>>>(x, xhi, xlo, n1,
                                                in_w, wihi, wilo, n2,
                                                out_w, wohi, wolo, n3);
        cvt_wpad_kernel<<<(kNPP * kDI + 255) / 256, 256>>>(xproj_w);
    }

    // GEMM1: xz = x @ in_w^T + in_b   (M=2048, N=4096, K=1024)
    {
        dim3 grid((2 * kDI) / 128, kRows / 128, 1);
        gemm_bf16x3_kernel<true><<<grid, 256, TC_SMEM>>>(
            xhi, xlo, wihi, wilo, in_b, xz_p, nullptr, 0, kDM, kDM, 2 * kDI);
    }
    // conv + SiLU gate (also emits xh hi/lo)
    conv_gate_kernel<<<(kRows * kDI) / 256, 256>>>(conv_w, conv_b);
    // xproj via MMA GEMM: proj_padded = xh @ wpad^T, split-K=8, then combine
    {
        dim3 grid(1, kRows / 128, kPKS);
        gemm_bf16x3_kernel<false><<<grid, 256, TC_SMEM>>>(
            xhhi, xhlo, wphi, wplo, nullptr,
            projp_p, projp_p + (size_t)kRows * kNPP, (size_t)kRows * kNPP,
            kDI, kDI / kPKS, kNPP);
        proj_combine_kernel<<<(kRows * kNP + 255) / 256, 256>>>();
    }
    // chunked selective scan (pass3 emits y as bf16 hi/lo)
    {
        const int grid_scan = kB * kNCH * (kDI / 256);   // 1024
        scan_pass1_kernel<<<grid_scan, 256>>>(dt_w, dt_b, A_log);
        scan_combine_kernel<<<(kB * kDI * kDS) / 256, 256>>>();
        scan_pass3_kernel<<<grid_scan, 256>>>(dt_w, dt_b, A_log, Dv);
    }
    // GEMM2: out = y @ out_w^T  (M=2048, N=1024, K=2048), split-K=2
    {
        dim3 grid(kDM / 128, kRows / 128, 2);
        gemm_bf16x3_kernel<false><<<grid, 256, TC_SMEM>>>(
            yhi, ylo, wohi, wolo, nullptr, out, part_p, 0, kDI, kDI / 2, kDM);
        add_kernel<<<(kRows * kDM / 4 + 255) / 256, 256>>>(out, part_p, kRows * kDM / 4);
    }
}